// round 4
// baseline (speedup 1.0000x reference)
#include <cuda_runtime.h>
#include <math.h>

#define T_TOKENS 131072   // 32 * 64 * 64

// ---------------- scratch (device globals, no allocation) ----------------
__device__ float  g_xr [T_TOKENS * 128];   // 64 MB
__device__ float  g_qkv[T_TOKENS * 384];   // 192 MB
__device__ float  g_att[T_TOKENS * 128];   // 64 MB
__device__ float2 g_st [T_TOKENS];         // 1 MB  (mu, rstd)

// ---------------- helpers ----------------
__device__ __forceinline__ unsigned f2tf32(float x) {
    unsigned r; asm("cvt.rna.tf32.f32 %0, %1;" : "=r"(r) : "f"(x)); return r;
}
__device__ __forceinline__ void mma_tf32(float c[4], const unsigned a[4], const unsigned b[2]) {
    asm volatile(
        "mma.sync.aligned.m16n8k8.row.col.f32.tf32.tf32.f32 "
        "{%0,%1,%2,%3}, {%4,%5,%6,%7}, {%8,%9}, {%0,%1,%2,%3};\n"
        : "+f"(c[0]), "+f"(c[1]), "+f"(c[2]), "+f"(c[3])
        : "r"(a[0]), "r"(a[1]), "r"(a[2]), "r"(a[3]), "r"(b[0]), "r"(b[1]));
}
__device__ __forceinline__ float gelu_exact(float x) {
    return 0.5f * x * (1.0f + erff(x * 0.70710678118654752f));
}

// ---------------- transpose (B,C,HW) -> (B,HW,C) ----------------
__global__ void k_transpose(const float* __restrict__ x, float* __restrict__ xr) {
    __shared__ float tile[32][33];
    int b  = blockIdx.z;
    int s0 = blockIdx.x * 32;
    int c0 = blockIdx.y * 32;
    const float* xb = x + (size_t)b * 128 * 4096;
    int tx = threadIdx.x, ty = threadIdx.y;  // 32 x 8
#pragma unroll
    for (int i = 0; i < 32; i += 8)
        tile[ty + i][tx] = xb[(size_t)(c0 + ty + i) * 4096 + s0 + tx];
    __syncthreads();
    float* xrb = xr + (size_t)b * 4096 * 128;
#pragma unroll
    for (int i = 0; i < 32; i += 8)
        xrb[(size_t)(s0 + ty + i) * 128 + c0 + tx] = tile[tx][ty + i];
}

// ---------------- LN stats: one warp per token (C=128) ----------------
__global__ void k_lnstats(const float* __restrict__ in, float2* __restrict__ st) {
    int warp = (blockIdx.x * blockDim.x + threadIdx.x) >> 5;
    int lane = threadIdx.x & 31;
    if (warp >= T_TOKENS) return;
    float4 v = ((const float4*)(in + (size_t)warp * 128))[lane];
    float s = v.x + v.y + v.z + v.w;
#pragma unroll
    for (int o = 16; o; o >>= 1) s += __shfl_xor_sync(0xffffffffu, s, o);
    float mu = s * (1.0f / 128.0f);
    float dx = v.x - mu, dy = v.y - mu, dz = v.z - mu, dw = v.w - mu;
    float q = dx * dx + dy * dy + dz * dz + dw * dw;
#pragma unroll
    for (int o = 16; o; o >>= 1) q += __shfl_xor_sync(0xffffffffu, q, o);
    float rstd = rsqrtf(q * (1.0f / 128.0f) + 1e-5f);
    if (lane == 0) { float2 o2; o2.x = mu; o2.y = rstd; st[warp] = o2; }
}

// ---------------- tf32 GEMM (optional fused LN on A, gelu, residual) ----------------
// BM=128, BN=128, BK=32, 256 threads, warp tile 32x64.
template <bool LNA, int ACT, bool RES>
__global__ __launch_bounds__(256)
void k_gemm_t(const float* __restrict__ A, const float2* __restrict__ stats,
              const float* __restrict__ lng, const float* __restrict__ lnb,
              const float* __restrict__ B, const float* __restrict__ bias,
              const float* __restrict__ res, float* __restrict__ C,
              int M, int N, int K) {
    __shared__ float As[128][36];
    __shared__ float Bs[32][136];

    const int tid  = threadIdx.x;
    const int lane = tid & 31;
    const int wid  = tid >> 5;
    const int wm   = (wid >> 1) * 32;
    const int wn   = (wid & 1) * 64;
    const int g    = lane >> 2;
    const int tg   = lane & 3;
    const size_t bm = (size_t)blockIdx.x * 128;
    const size_t bn = (size_t)blockIdx.y * 128;

    const int am  = tid >> 3;
    const int ak  = (tid & 7) * 4;
    const int bk  = tid >> 5;
    const int bnn = (tid & 31) * 4;

    const float* Ag = A + (bm + am) * (size_t)K + ak;
    const float* Bg = B + (size_t)bk * N + bn + bnn;

    float2 st4[4];
    if (LNA) {
#pragma unroll
        for (int p = 0; p < 4; ++p) st4[p] = stats[bm + am + p * 32];
    }

    float acc[2][8][4];
#pragma unroll
    for (int i = 0; i < 2; ++i)
#pragma unroll
        for (int j = 0; j < 8; ++j)
#pragma unroll
            for (int r = 0; r < 4; ++r) acc[i][j][r] = 0.f;

    const int KT = K >> 5;

    // preload tile 0
    {
        float4 gv, bv;
        if (LNA) { gv = *(const float4*)(lng + ak); bv = *(const float4*)(lnb + ak); }
#pragma unroll
        for (int p = 0; p < 4; ++p) {
            float4 av = *(const float4*)(Ag + (size_t)(p * 32) * K);
            if (LNA) {
                float2 s = st4[p];
                av.x = (av.x - s.x) * s.y * gv.x + bv.x;
                av.y = (av.y - s.x) * s.y * gv.y + bv.y;
                av.z = (av.z - s.x) * s.y * gv.z + bv.z;
                av.w = (av.w - s.x) * s.y * gv.w + bv.w;
            }
            *(float4*)&As[am + p * 32][ak] = av;
            *(float4*)&Bs[bk + p * 8][bnn] = *(const float4*)(Bg + (size_t)(p * 8) * N);
        }
    }
    __syncthreads();

    for (int kt = 0; kt < KT; ++kt) {
        float4 pa[4], pb[4];
        const bool nxt = (kt + 1 < KT);
        if (nxt) {
            const float* An = Ag + (size_t)(kt + 1) * 32;
            const float* Bn = Bg + (size_t)(kt + 1) * 32 * N;
            float4 gv, bv;
            if (LNA) {
                gv = *(const float4*)(lng + (kt + 1) * 32 + ak);
                bv = *(const float4*)(lnb + (kt + 1) * 32 + ak);
            }
#pragma unroll
            for (int p = 0; p < 4; ++p) {
                float4 av = *(const float4*)(An + (size_t)(p * 32) * K);
                if (LNA) {
                    float2 s = st4[p];
                    av.x = (av.x - s.x) * s.y * gv.x + bv.x;
                    av.y = (av.y - s.x) * s.y * gv.y + bv.y;
                    av.z = (av.z - s.x) * s.y * gv.z + bv.z;
                    av.w = (av.w - s.x) * s.y * gv.w + bv.w;
                }
                pa[p] = av;
                pb[p] = *(const float4*)(Bn + (size_t)(p * 8) * N);
            }
        }
#pragma unroll
        for (int ks = 0; ks < 4; ++ks) {
            const int kk = ks * 8;
            unsigned af[2][4];
#pragma unroll
            for (int mi = 0; mi < 2; ++mi) {
                const int m0 = wm + mi * 16 + g;
                af[mi][0] = f2tf32(As[m0    ][kk + tg]);
                af[mi][1] = f2tf32(As[m0 + 8][kk + tg]);
                af[mi][2] = f2tf32(As[m0    ][kk + tg + 4]);
                af[mi][3] = f2tf32(As[m0 + 8][kk + tg + 4]);
            }
            unsigned bf[8][2];
#pragma unroll
            for (int ni = 0; ni < 8; ++ni) {
                const int n0 = wn + ni * 8 + g;
                bf[ni][0] = f2tf32(Bs[kk + tg    ][n0]);
                bf[ni][1] = f2tf32(Bs[kk + tg + 4][n0]);
            }
#pragma unroll
            for (int mi = 0; mi < 2; ++mi)
#pragma unroll
                for (int ni = 0; ni < 8; ++ni)
                    mma_tf32(acc[mi][ni], af[mi], bf[ni]);
        }
        __syncthreads();
        if (nxt) {
#pragma unroll
            for (int p = 0; p < 4; ++p) {
                *(float4*)&As[am + p * 32][ak] = pa[p];
                *(float4*)&Bs[bk + p * 8][bnn] = pb[p];
            }
            __syncthreads();
        }
    }

#pragma unroll
    for (int mi = 0; mi < 2; ++mi) {
        const size_t r0 = bm + wm + mi * 16 + g;
#pragma unroll
        for (int ni = 0; ni < 8; ++ni) {
            const size_t c0 = bn + wn + ni * 8 + 2 * tg;
            const float bx = bias[c0], by = bias[c0 + 1];
            float v0 = acc[mi][ni][0] + bx, v1 = acc[mi][ni][1] + by;
            float v2 = acc[mi][ni][2] + bx, v3 = acc[mi][ni][3] + by;
            if (ACT == 1) {
                v0 = gelu_exact(v0); v1 = gelu_exact(v1);
                v2 = gelu_exact(v2); v3 = gelu_exact(v3);
            }
            const size_t o0 = r0 * N + c0;
            const size_t o1 = (r0 + 8) * N + c0;
            if (RES) {
                float2 ra = *(const float2*)(res + o0);
                float2 rb = *(const float2*)(res + o1);
                v0 += ra.x; v1 += ra.y; v2 += rb.x; v3 += rb.y;
            }
            float2 w0; w0.x = v0; w0.y = v1;
            float2 w1; w1.x = v2; w1.y = v3;
            *(float2*)(C + o0) = w0;
            *(float2*)(C + o1) = w1;
        }
    }
}

// ---------------- fused MLP: y += W2 @ gelu(W1 @ LN(y) + b1) + b2 ----------------
// One block per 64 tokens. 512 threads (16 warps). Hidden kept in smem.
// smem: sA [64][132] (LN(y)), sB [32][264] (W1 chunk), sH [64][516] (hidden).
// GEMM2 reuses sA region as [32][136] for W2 chunks.
#define MLP_SMEM ((64*132 + 32*264 + 64*516) * 4)

__global__ __launch_bounds__(512)
void k_mlp(float* __restrict__ y,
           const float* __restrict__ lng, const float* __restrict__ lnb,
           const float* __restrict__ W1, const float* __restrict__ b1,
           const float* __restrict__ W2, const float* __restrict__ b2) {
    extern __shared__ float sm[];
    float* sA = sm;                    // 64 x 132
    float* sB = sm + 64 * 132;         // 32 x 264
    float* sH = sB + 32 * 264;         // 64 x 516

    const int tid  = threadIdx.x;
    const int lane = tid & 31;
    const int wid  = tid >> 5;
    const int g    = lane >> 2;
    const int tg   = lane & 3;
    const size_t bm = (size_t)blockIdx.x * 64;

    // phase 0: load y tile (raw)
#pragma unroll
    for (int q = 0; q < 4; ++q) {
        int f4 = q * 512 + tid;              // 0..2047
        int r = f4 >> 5, c = (f4 & 31) * 4;
        *(float4*)&sA[r * 132 + c] = *(const float4*)(y + (bm + r) * 128 + c);
    }
    __syncthreads();

    // LN in place: warp per 4 rows
#pragma unroll
    for (int rr = 0; rr < 4; ++rr) {
        int r = wid * 4 + rr;
        float4 v = *(float4*)&sA[r * 132 + lane * 4];
        float s = v.x + v.y + v.z + v.w;
#pragma unroll
        for (int o = 16; o; o >>= 1) s += __shfl_xor_sync(0xffffffffu, s, o);
        float mu = s * (1.0f / 128.0f);
        float dx = v.x - mu, dy = v.y - mu, dz = v.z - mu, dw = v.w - mu;
        float q2 = dx * dx + dy * dy + dz * dz + dw * dw;
#pragma unroll
        for (int o = 16; o; o >>= 1) q2 += __shfl_xor_sync(0xffffffffu, q2, o);
        float rstd = rsqrtf(q2 * (1.0f / 128.0f) + 1e-5f);
        float4 gv = __ldg((const float4*)lng + lane);
        float4 bv = __ldg((const float4*)lnb + lane);
        float4 o4;
        o4.x = dx * rstd * gv.x + bv.x;
        o4.y = dy * rstd * gv.y + bv.y;
        o4.z = dz * rstd * gv.z + bv.z;
        o4.w = dw * rstd * gv.w + bv.w;
        *(float4*)&sA[r * 132 + lane * 4] = o4;
    }
    __syncthreads();

    // GEMM1: sH[64][512] = gelu(sA[64][128] @ W1[128][512] + b1), two N-halves of 256
    const int wm = (wid & 1) * 32;
    const int wn = (wid >> 1) * 32;
#pragma unroll 1
    for (int p = 0; p < 2; ++p) {
        float acc[2][4][4];
#pragma unroll
        for (int i = 0; i < 2; ++i)
#pragma unroll
            for (int j = 0; j < 4; ++j)
#pragma unroll
                for (int r = 0; r < 4; ++r) acc[i][j][r] = 0.f;
#pragma unroll 1
        for (int kt = 0; kt < 4; ++kt) {
#pragma unroll
            for (int q = 0; q < 4; ++q) {
                int f4 = q * 512 + tid;          // 0..2047
                int r = f4 >> 6, c = (f4 & 63) * 4;
                *(float4*)&sB[r * 264 + c] =
                    *(const float4*)(W1 + (size_t)(kt * 32 + r) * 512 + p * 256 + c);
            }
            __syncthreads();
#pragma unroll
            for (int ks = 0; ks < 4; ++ks) {
                const int kk = kt * 32 + ks * 8;
                const int kl = ks * 8;
                unsigned af[2][4];
#pragma unroll
                for (int mi = 0; mi < 2; ++mi) {
                    const int m0 = wm + mi * 16 + g;
                    af[mi][0] = f2tf32(sA[m0 * 132 + kk + tg]);
                    af[mi][1] = f2tf32(sA[(m0 + 8) * 132 + kk + tg]);
                    af[mi][2] = f2tf32(sA[m0 * 132 + kk + tg + 4]);
                    af[mi][3] = f2tf32(sA[(m0 + 8) * 132 + kk + tg + 4]);
                }
                unsigned bf[4][2];
#pragma unroll
                for (int ni = 0; ni < 4; ++ni) {
                    const int n0 = wn + ni * 8 + g;
                    bf[ni][0] = f2tf32(sB[(kl + tg) * 264 + n0]);
                    bf[ni][1] = f2tf32(sB[(kl + tg + 4) * 264 + n0]);
                }
#pragma unroll
                for (int mi = 0; mi < 2; ++mi)
#pragma unroll
                    for (int ni = 0; ni < 4; ++ni)
                        mma_tf32(acc[mi][ni], af[mi], bf[ni]);
            }
            __syncthreads();
        }
        // epilogue: gelu -> sH
#pragma unroll
        for (int mi = 0; mi < 2; ++mi) {
            const int r0 = wm + mi * 16 + g;
#pragma unroll
            for (int ni = 0; ni < 4; ++ni) {
                const int c0 = wn + ni * 8 + 2 * tg;
                const float bx = __ldg(b1 + p * 256 + c0);
                const float by = __ldg(b1 + p * 256 + c0 + 1);
                float2 w0, w1;
                w0.x = gelu_exact(acc[mi][ni][0] + bx);
                w0.y = gelu_exact(acc[mi][ni][1] + by);
                w1.x = gelu_exact(acc[mi][ni][2] + bx);
                w1.y = gelu_exact(acc[mi][ni][3] + by);
                *(float2*)&sH[r0 * 516 + p * 256 + c0] = w0;
                *(float2*)&sH[(r0 + 8) * 516 + p * 256 + c0] = w1;
            }
        }
        __syncthreads();
    }

    // GEMM2: C[64][128] = sH[64][512] @ W2[512][128] + b2 + y   (W2 chunks in sA region)
    float* sB2 = sA;  // [32][136]
    const int wn2 = (wid >> 1) * 16;
    float acc2[2][2][4];
#pragma unroll
    for (int i = 0; i < 2; ++i)
#pragma unroll
        for (int j = 0; j < 2; ++j)
#pragma unroll
            for (int r = 0; r < 4; ++r) acc2[i][j][r] = 0.f;
#pragma unroll 1
    for (int kt = 0; kt < 16; ++kt) {
#pragma unroll
        for (int q = 0; q < 2; ++q) {
            int f4 = q * 512 + tid;              // 0..1023
            int r = f4 >> 5, c = (f4 & 31) * 4;
            *(float4*)&sB2[r * 136 + c] =
                *(const float4*)(W2 + (size_t)(kt * 32 + r) * 128 + c);
        }
        __syncthreads();
#pragma unroll
        for (int ks = 0; ks < 4; ++ks) {
            const int kk = kt * 32 + ks * 8;
            const int kl = ks * 8;
            unsigned af[2][4];
#pragma unroll
            for (int mi = 0; mi < 2; ++mi) {
                const int m0 = wm + mi * 16 + g;
                af[mi][0] = f2tf32(sH[m0 * 516 + kk + tg]);
                af[mi][1] = f2tf32(sH[(m0 + 8) * 516 + kk + tg]);
                af[mi][2] = f2tf32(sH[m0 * 516 + kk + tg + 4]);
                af[mi][3] = f2tf32(sH[(m0 + 8) * 516 + kk + tg + 4]);
            }
            unsigned bf[2][2];
#pragma unroll
            for (int ni = 0; ni < 2; ++ni) {
                const int n0 = wn2 + ni * 8 + g;
                bf[ni][0] = f2tf32(sB2[(kl + tg) * 136 + n0]);
                bf[ni][1] = f2tf32(sB2[(kl + tg + 4) * 136 + n0]);
            }
#pragma unroll
            for (int mi = 0; mi < 2; ++mi)
#pragma unroll
                for (int ni = 0; ni < 2; ++ni)
                    mma_tf32(acc2[mi][ni], af[mi], bf[ni]);
        }
        __syncthreads();
    }
    // epilogue: += b2 + residual(y), write y
#pragma unroll
    for (int mi = 0; mi < 2; ++mi) {
        const size_t r0 = bm + wm + mi * 16 + g;
#pragma unroll
        for (int ni = 0; ni < 2; ++ni) {
            const int c0 = wn2 + ni * 8 + 2 * tg;
            const float bx = __ldg(b2 + c0), by = __ldg(b2 + c0 + 1);
            const size_t o0 = r0 * 128 + c0;
            const size_t o1 = (r0 + 8) * 128 + c0;
            float2 ra = *(const float2*)(y + o0);
            float2 rb = *(const float2*)(y + o1);
            float2 w0, w1;
            w0.x = acc2[mi][ni][0] + bx + ra.x;
            w0.y = acc2[mi][ni][1] + by + ra.y;
            w1.x = acc2[mi][ni][2] + bx + rb.x;
            w1.y = acc2[mi][ni][3] + by + rb.y;
            *(float2*)(y + o0) = w0;
            *(float2*)(y + o1) = w1;
        }
    }
}

// ---------------- window attention (ws=2, n=4, heads=4, e=32) ----------------
__global__ __launch_bounds__(128)
void k_attn(const float* __restrict__ qkv, const float* __restrict__ pos,
            float* __restrict__ att, int shifted) {
    int wid = blockIdx.x;
    int ww = wid & 31, wh = (wid >> 5) & 31, b = wid >> 10;
    __shared__ float s[4][384];
    __shared__ float spos[9];
    int tid = threadIdx.x;
    if (tid < 9) spos[tid] = pos[tid];
    {
        int i = tid >> 5, lane = tid & 31;
        int lh = i >> 1, lw = i & 1;
        int h = wh * 2 + lh, w = ww * 2 + lw;
        if (shifted) { h = (h + 1) & 63; w = (w + 1) & 63; }
        size_t t = (size_t)b * 4096 + h * 64 + w;
        const float* src = qkv + t * 384;
#pragma unroll
        for (int j = 0; j < 12; ++j) s[i][lane + j * 32] = src[lane + j * 32];
    }
    __syncthreads();

    int head = tid >> 5, lane = tid & 31;
    float q[4], k[4], v[4];
#pragma unroll
    for (int i = 0; i < 4; ++i) {
        int base = (lane * 4 + head) * 3;
        q[i] = s[i][base]; k[i] = s[i][base + 1]; v[i] = s[i][base + 2];
    }
    const float scale = 0.17677669529663687f;
    float sc[4][4];
#pragma unroll
    for (int i = 0; i < 4; ++i)
#pragma unroll
        for (int j = 0; j < 4; ++j) {
            float p = q[i] * k[j];
#pragma unroll
            for (int o = 16; o; o >>= 1) p += __shfl_xor_sync(0xffffffffu, p, o);
            int dx = (j >> 1) - (i >> 1) + 1;
            int dy = (j & 1) - (i & 1) + 1;
            float w = p * scale + spos[dx * 3 + dy];
            if (shifted) {
                if (wh == 31 && ((i >> 1) != (j >> 1))) w = -1e30f;
                if (ww == 31 && ((i & 1) != (j & 1))) w = -1e30f;
            }
            sc[i][j] = w;
        }
    float out[4];
#pragma unroll
    for (int i = 0; i < 4; ++i) {
        float m = fmaxf(fmaxf(sc[i][0], sc[i][1]), fmaxf(sc[i][2], sc[i][3]));
        float e0 = expf(sc[i][0] - m), e1 = expf(sc[i][1] - m);
        float e2 = expf(sc[i][2] - m), e3 = expf(sc[i][3] - m);
        float inv = 1.0f / (e0 + e1 + e2 + e3);
        out[i] = (e0 * v[0] + e1 * v[1] + e2 * v[2] + e3 * v[3]) * inv;
    }
#pragma unroll
    for (int i = 0; i < 4; ++i) {
        int lh = i >> 1, lw = i & 1;
        int h = wh * 2 + lh, w = ww * 2 + lw;
        size_t t = (size_t)b * 4096 + h * 64 + w;
        att[t * 128 + head * 32 + lane] = out[i];
    }
}

// ---------------- host orchestration ----------------
extern "C" void kernel_launch(void* const* d_in, const int* in_sizes, int n_in,
                              void* d_out, int out_size) {
    const float* x    = (const float*)d_in[0];
    const float* ln_g = (const float*)d_in[1];
    const float* ln_b = (const float*)d_in[2];
    const float* wq_W = (const float*)d_in[3];
    const float* wq_b = (const float*)d_in[4];
    const float* wp_W = (const float*)d_in[5];
    const float* wp_b = (const float*)d_in[6];
    const float* wpos = (const float*)d_in[7];
    const float* sq_W = (const float*)d_in[8];
    const float* sq_b = (const float*)d_in[9];
    const float* sp_W = (const float*)d_in[10];
    const float* sp_b = (const float*)d_in[11];
    const float* spos = (const float*)d_in[12];
    const float* m1_W = (const float*)d_in[13];
    const float* m1_b = (const float*)d_in[14];
    const float* m2_W = (const float*)d_in[15];
    const float* m2_b = (const float*)d_in[16];
    float* y = (float*)d_out;

    float *p_xr, *p_qkv, *p_att;
    float2* p_st;
    cudaGetSymbolAddress((void**)&p_xr,  g_xr);
    cudaGetSymbolAddress((void**)&p_qkv, g_qkv);
    cudaGetSymbolAddress((void**)&p_att, g_att);
    cudaGetSymbolAddress((void**)&p_st,  g_st);

    static bool s_attr = false;
    if (!s_attr) {
        cudaFuncSetAttribute(k_mlp, cudaFuncAttributeMaxDynamicSharedMemorySize, MLP_SMEM);
        s_attr = true;
    }

    const int M = T_TOKENS;
    dim3 tgrid(128, 4, 32), tblk(32, 8);
    int lnGrid = T_TOKENS / 8;

    k_transpose<<<tgrid, tblk>>>(x, p_xr);

    // ---- block 1: W-MSA ----
    k_lnstats<<<lnGrid, 256>>>(p_xr, p_st);
    k_gemm_t<true, 0, false><<<dim3(M / 128, 3), 256>>>(p_xr, p_st, ln_g, ln_b, wq_W, wq_b, nullptr, p_qkv, M, 384, 128);
    k_attn<<<32768, 128>>>(p_qkv, wpos, p_att, 0);
    k_gemm_t<false, 0, true><<<dim3(M / 128, 1), 256>>>(p_att, nullptr, nullptr, nullptr, wp_W, wp_b, p_xr, y, M, 128, 128);
    k_mlp<<<M / 64, 512, MLP_SMEM>>>(y, ln_g, ln_b, m1_W, m1_b, m2_W, m2_b);

    // ---- block 2: SW-MSA ----
    k_lnstats<<<lnGrid, 256>>>(y, p_st);
    k_gemm_t<true, 0, false><<<dim3(M / 128, 3), 256>>>(y, p_st, ln_g, ln_b, sq_W, sq_b, nullptr, p_qkv, M, 384, 128);
    k_attn<<<32768, 128>>>(p_qkv, spos, p_att, 1);
    k_gemm_t<false, 0, true><<<dim3(M / 128, 1), 256>>>(p_att, nullptr, nullptr, nullptr, sp_W, sp_b, y, y, M, 128, 128);
    k_mlp<<<M / 64, 512, MLP_SMEM>>>(y, ln_g, ln_b, m1_W, m1_b, m2_W, m2_b);
}

// round 5
// speedup vs baseline: 1.3195x; 1.3195x over previous
#include <cuda_runtime.h>
#include <math.h>

#define T_TOKENS 131072   // 32 * 64 * 64

// ---------------- scratch (device globals, no allocation) ----------------
__device__ float  g_xr [T_TOKENS * 128];   // 64 MB
__device__ float  g_qkv[T_TOKENS * 384];   // 192 MB
__device__ float  g_att[T_TOKENS * 128];   // 64 MB
__device__ float  g_h  [T_TOKENS * 512];   // 256 MB
__device__ float2 g_st [T_TOKENS];         // 1 MB  (mu, rstd)

// ---------------- helpers ----------------
__device__ __forceinline__ unsigned f2tf32(float x) {
    unsigned r; asm("cvt.rna.tf32.f32 %0, %1;" : "=r"(r) : "f"(x)); return r;
}
__device__ __forceinline__ void mma_tf32(float c[4], const unsigned a[4], const unsigned b[2]) {
    asm volatile(
        "mma.sync.aligned.m16n8k8.row.col.f32.tf32.tf32.f32 "
        "{%0,%1,%2,%3}, {%4,%5,%6,%7}, {%8,%9}, {%0,%1,%2,%3};\n"
        : "+f"(c[0]), "+f"(c[1]), "+f"(c[2]), "+f"(c[3])
        : "r"(a[0]), "r"(a[1]), "r"(a[2]), "r"(a[3]), "r"(b[0]), "r"(b[1]));
}
__device__ __forceinline__ float gelu_exact(float x) {
    return 0.5f * x * (1.0f + erff(x * 0.70710678118654752f));
}
__device__ __forceinline__ void cp16(float* dst, const float* src) {
    unsigned s = (unsigned)__cvta_generic_to_shared(dst);
    asm volatile("cp.async.cg.shared.global [%0], [%1], 16;\n" :: "r"(s), "l"(src));
}
__device__ __forceinline__ void cp_commit() {
    asm volatile("cp.async.commit_group;\n");
}
__device__ __forceinline__ void cp_wait0() {
    asm volatile("cp.async.wait_group 0;\n");
}

// ---------------- transpose (B,C,HW) -> (B,HW,C) ----------------
__global__ void k_transpose(const float* __restrict__ x, float* __restrict__ xr) {
    __shared__ float tile[32][33];
    int b  = blockIdx.z;
    int s0 = blockIdx.x * 32;
    int c0 = blockIdx.y * 32;
    const float* xb = x + (size_t)b * 128 * 4096;
    int tx = threadIdx.x, ty = threadIdx.y;  // 32 x 8
#pragma unroll
    for (int i = 0; i < 32; i += 8)
        tile[ty + i][tx] = xb[(size_t)(c0 + ty + i) * 4096 + s0 + tx];
    __syncthreads();
    float* xrb = xr + (size_t)b * 4096 * 128;
#pragma unroll
    for (int i = 0; i < 32; i += 8)
        xrb[(size_t)(s0 + ty + i) * 128 + c0 + tx] = tile[tx][ty + i];
}

// ---------------- LN stats: one warp per token (C=128) ----------------
__global__ void k_lnstats(const float* __restrict__ in, float2* __restrict__ st) {
    int warp = (blockIdx.x * blockDim.x + threadIdx.x) >> 5;
    int lane = threadIdx.x & 31;
    if (warp >= T_TOKENS) return;
    float4 v = ((const float4*)(in + (size_t)warp * 128))[lane];
    float s = v.x + v.y + v.z + v.w;
#pragma unroll
    for (int o = 16; o; o >>= 1) s += __shfl_xor_sync(0xffffffffu, s, o);
    float mu = s * (1.0f / 128.0f);
    float dx = v.x - mu, dy = v.y - mu, dz = v.z - mu, dw = v.w - mu;
    float q = dx * dx + dy * dy + dz * dz + dw * dw;
#pragma unroll
    for (int o = 16; o; o >>= 1) q += __shfl_xor_sync(0xffffffffu, q, o);
    float rstd = rsqrtf(q * (1.0f / 128.0f) + 1e-5f);
    if (lane == 0) { float2 o2; o2.x = mu; o2.y = rstd; st[warp] = o2; }
}

// ---------------- tf32 GEMM, 2-stage cp.async pipeline ----------------
// C[M,N] = [gelu|id](LN?(A)[M,K] @ B[K,N] + bias) (+res). M%128==0, N%128==0, K%32==0.
// BM=128, BN=128, BK=32, 256 threads, warp tile 32x64.
// Dynamic smem: As[2][128][36] + Bs[2][32][136] = 71680 B.
#define GEMM_SMEM ((2 * 128 * 36 + 2 * 32 * 136) * 4)
#define AS_OFF(buf, r, c) ((buf) * (128 * 36) + (r) * 36 + (c))
#define BS_OFF(buf, r, c) (2 * 128 * 36 + (buf) * (32 * 136) + (r) * 136 + (c))

template <bool LNA, int ACT, bool RES>
__global__ __launch_bounds__(256, 2)
void k_gemm_t(const float* __restrict__ A, const float2* __restrict__ stats,
              const float* __restrict__ lng, const float* __restrict__ lnb,
              const float* __restrict__ B, const float* __restrict__ bias,
              const float* __restrict__ res, float* __restrict__ C,
              int M, int N, int K) {
    extern __shared__ float sm[];

    const int tid  = threadIdx.x;
    const int lane = tid & 31;
    const int wid  = tid >> 5;
    const int wm   = (wid >> 1) * 32;
    const int wn   = (wid & 1) * 64;
    const int g    = lane >> 2;
    const int tg   = lane & 3;
    const size_t bm = (size_t)blockIdx.x * 128;
    const size_t bn = (size_t)blockIdx.y * 128;

    const int am  = tid >> 3;           // 0..31 (A row within 32-row pass)
    const int ak  = (tid & 7) * 4;      // k offset (float4)
    const int bk  = tid >> 5;           // 0..7  (B k-row within 8-row pass)
    const int bnn = (tid & 31) * 4;     // n offset (float4)

    const float* Ag = A + (bm + am) * (size_t)K + ak;
    const float* Bg = B + (size_t)bk * N + bn + bnn;

    float2 st4[4];
    if (LNA) {
#pragma unroll
        for (int p = 0; p < 4; ++p) st4[p] = stats[bm + am + p * 32];
    }

    float acc[2][8][4];
#pragma unroll
    for (int i = 0; i < 2; ++i)
#pragma unroll
        for (int j = 0; j < 8; ++j)
#pragma unroll
            for (int r = 0; r < 4; ++r) acc[i][j][r] = 0.f;

    const int KT = K >> 5;

    // ---- prologue: tile 0 into buf 0 ----
    if (LNA) {
        float4 gv = *(const float4*)(lng + ak);
        float4 bv = *(const float4*)(lnb + ak);
#pragma unroll
        for (int p = 0; p < 4; ++p) {
            float4 av = *(const float4*)(Ag + (size_t)(p * 32) * K);
            float2 s = st4[p];
            av.x = (av.x - s.x) * s.y * gv.x + bv.x;
            av.y = (av.y - s.x) * s.y * gv.y + bv.y;
            av.z = (av.z - s.x) * s.y * gv.z + bv.z;
            av.w = (av.w - s.x) * s.y * gv.w + bv.w;
            *(float4*)&sm[AS_OFF(0, am + p * 32, ak)] = av;
        }
    } else {
#pragma unroll
        for (int p = 0; p < 4; ++p)
            cp16(&sm[AS_OFF(0, am + p * 32, ak)], Ag + (size_t)(p * 32) * K);
    }
#pragma unroll
    for (int p = 0; p < 4; ++p)
        cp16(&sm[BS_OFF(0, bk + p * 8, bnn)], Bg + (size_t)(p * 8) * N);
    cp_commit();
    cp_wait0();
    __syncthreads();

    // ---- main loop: 1 sync per k-tile ----
    int buf = 0;
    for (int kt = 0; kt < KT; ++kt, buf ^= 1) {
        const bool nxt = (kt + 1 < KT);
        float4 pa[4];
        if (nxt) {
            const float* Bn = Bg + (size_t)(kt + 1) * 32 * N;
#pragma unroll
            for (int p = 0; p < 4; ++p)
                cp16(&sm[BS_OFF(buf ^ 1, bk + p * 8, bnn)], Bn + (size_t)(p * 8) * N);
            if (!LNA) {
                const float* An = Ag + (size_t)(kt + 1) * 32;
#pragma unroll
                for (int p = 0; p < 4; ++p)
                    cp16(&sm[AS_OFF(buf ^ 1, am + p * 32, ak)], An + (size_t)(p * 32) * K);
            }
            cp_commit();
            if (LNA) {
                const float* An = Ag + (size_t)(kt + 1) * 32;
                float4 gv = *(const float4*)(lng + (kt + 1) * 32 + ak);
                float4 bv = *(const float4*)(lnb + (kt + 1) * 32 + ak);
#pragma unroll
                for (int p = 0; p < 4; ++p) {
                    float4 av = *(const float4*)(An + (size_t)(p * 32) * K);
                    float2 s = st4[p];
                    av.x = (av.x - s.x) * s.y * gv.x + bv.x;
                    av.y = (av.y - s.x) * s.y * gv.y + bv.y;
                    av.z = (av.z - s.x) * s.y * gv.z + bv.z;
                    av.w = (av.w - s.x) * s.y * gv.w + bv.w;
                    pa[p] = av;
                }
            }
        }
        // compute on buf
#pragma unroll
        for (int ks = 0; ks < 4; ++ks) {
            const int kk = ks * 8;
            unsigned af[2][4];
#pragma unroll
            for (int mi = 0; mi < 2; ++mi) {
                const int m0 = wm + mi * 16 + g;
                af[mi][0] = f2tf32(sm[AS_OFF(buf, m0,     kk + tg)]);
                af[mi][1] = f2tf32(sm[AS_OFF(buf, m0 + 8, kk + tg)]);
                af[mi][2] = f2tf32(sm[AS_OFF(buf, m0,     kk + tg + 4)]);
                af[mi][3] = f2tf32(sm[AS_OFF(buf, m0 + 8, kk + tg + 4)]);
            }
            unsigned bf[8][2];
#pragma unroll
            for (int ni = 0; ni < 8; ++ni) {
                const int n0 = wn + ni * 8 + g;
                bf[ni][0] = f2tf32(sm[BS_OFF(buf, kk + tg,     n0)]);
                bf[ni][1] = f2tf32(sm[BS_OFF(buf, kk + tg + 4, n0)]);
            }
#pragma unroll
            for (int mi = 0; mi < 2; ++mi)
#pragma unroll
                for (int ni = 0; ni < 8; ++ni)
                    mma_tf32(acc[mi][ni], af[mi], bf[ni]);
        }
        if (nxt) {
            if (LNA) {
#pragma unroll
                for (int p = 0; p < 4; ++p)
                    *(float4*)&sm[AS_OFF(buf ^ 1, am + p * 32, ak)] = pa[p];
            }
            cp_wait0();
            __syncthreads();
        }
    }

    // ---- epilogue ----
#pragma unroll
    for (int mi = 0; mi < 2; ++mi) {
        const size_t r0 = bm + wm + mi * 16 + g;
#pragma unroll
        for (int ni = 0; ni < 8; ++ni) {
            const size_t c0 = bn + wn + ni * 8 + 2 * tg;
            const float bx = bias[c0], by = bias[c0 + 1];
            float v0 = acc[mi][ni][0] + bx, v1 = acc[mi][ni][1] + by;
            float v2 = acc[mi][ni][2] + bx, v3 = acc[mi][ni][3] + by;
            if (ACT == 1) {
                v0 = gelu_exact(v0); v1 = gelu_exact(v1);
                v2 = gelu_exact(v2); v3 = gelu_exact(v3);
            }
            const size_t o0 = r0 * N + c0;
            const size_t o1 = (r0 + 8) * N + c0;
            if (RES) {
                float2 ra = *(const float2*)(res + o0);
                float2 rb = *(const float2*)(res + o1);
                v0 += ra.x; v1 += ra.y; v2 += rb.x; v3 += rb.y;
            }
            float2 w0; w0.x = v0; w0.y = v1;
            float2 w1; w1.x = v2; w1.y = v3;
            *(float2*)(C + o0) = w0;
            *(float2*)(C + o1) = w1;
        }
    }
}

// ---------------- window attention (ws=2, n=4, heads=4, e=32) ----------------
__global__ __launch_bounds__(128)
void k_attn(const float* __restrict__ qkv, const float* __restrict__ pos,
            float* __restrict__ att, int shifted) {
    int wid = blockIdx.x;
    int ww = wid & 31, wh = (wid >> 5) & 31, b = wid >> 10;
    __shared__ float s[4][384];
    __shared__ float spos[9];
    int tid = threadIdx.x;
    if (tid < 9) spos[tid] = pos[tid];
    {
        int i = tid >> 5, lane = tid & 31;
        int lh = i >> 1, lw = i & 1;
        int h = wh * 2 + lh, w = ww * 2 + lw;
        if (shifted) { h = (h + 1) & 63; w = (w + 1) & 63; }
        size_t t = (size_t)b * 4096 + h * 64 + w;
        const float* src = qkv + t * 384;
#pragma unroll
        for (int j = 0; j < 12; ++j) s[i][lane + j * 32] = src[lane + j * 32];
    }
    __syncthreads();

    int head = tid >> 5, lane = tid & 31;
    float q[4], k[4], v[4];
#pragma unroll
    for (int i = 0; i < 4; ++i) {
        int base = (lane * 4 + head) * 3;
        q[i] = s[i][base]; k[i] = s[i][base + 1]; v[i] = s[i][base + 2];
    }
    const float scale = 0.17677669529663687f;
    float sc[4][4];
#pragma unroll
    for (int i = 0; i < 4; ++i)
#pragma unroll
        for (int j = 0; j < 4; ++j) {
            float p = q[i] * k[j];
#pragma unroll
            for (int o = 16; o; o >>= 1) p += __shfl_xor_sync(0xffffffffu, p, o);
            int dx = (j >> 1) - (i >> 1) + 1;
            int dy = (j & 1) - (i & 1) + 1;
            float w = p * scale + spos[dx * 3 + dy];
            if (shifted) {
                if (wh == 31 && ((i >> 1) != (j >> 1))) w = -1e30f;
                if (ww == 31 && ((i & 1) != (j & 1))) w = -1e30f;
            }
            sc[i][j] = w;
        }
    float out[4];
#pragma unroll
    for (int i = 0; i < 4; ++i) {
        float m = fmaxf(fmaxf(sc[i][0], sc[i][1]), fmaxf(sc[i][2], sc[i][3]));
        float e0 = expf(sc[i][0] - m), e1 = expf(sc[i][1] - m);
        float e2 = expf(sc[i][2] - m), e3 = expf(sc[i][3] - m);
        float inv = 1.0f / (e0 + e1 + e2 + e3);
        out[i] = (e0 * v[0] + e1 * v[1] + e2 * v[2] + e3 * v[3]) * inv;
    }
#pragma unroll
    for (int i = 0; i < 4; ++i) {
        int lh = i >> 1, lw = i & 1;
        int h = wh * 2 + lh, w = ww * 2 + lw;
        size_t t = (size_t)b * 4096 + h * 64 + w;
        att[t * 128 + head * 32 + lane] = out[i];
    }
}

// ---------------- host orchestration ----------------
extern "C" void kernel_launch(void* const* d_in, const int* in_sizes, int n_in,
                              void* d_out, int out_size) {
    const float* x    = (const float*)d_in[0];
    const float* ln_g = (const float*)d_in[1];
    const float* ln_b = (const float*)d_in[2];
    const float* wq_W = (const float*)d_in[3];
    const float* wq_b = (const float*)d_in[4];
    const float* wp_W = (const float*)d_in[5];
    const float* wp_b = (const float*)d_in[6];
    const float* wpos = (const float*)d_in[7];
    const float* sq_W = (const float*)d_in[8];
    const float* sq_b = (const float*)d_in[9];
    const float* sp_W = (const float*)d_in[10];
    const float* sp_b = (const float*)d_in[11];
    const float* spos = (const float*)d_in[12];
    const float* m1_W = (const float*)d_in[13];
    const float* m1_b = (const float*)d_in[14];
    const float* m2_W = (const float*)d_in[15];
    const float* m2_b = (const float*)d_in[16];
    float* y = (float*)d_out;

    float *p_xr, *p_qkv, *p_att, *p_h;
    float2* p_st;
    cudaGetSymbolAddress((void**)&p_xr,  g_xr);
    cudaGetSymbolAddress((void**)&p_qkv, g_qkv);
    cudaGetSymbolAddress((void**)&p_att, g_att);
    cudaGetSymbolAddress((void**)&p_h,   g_h);
    cudaGetSymbolAddress((void**)&p_st,  g_st);

    static bool s_attr = false;
    if (!s_attr) {
        cudaFuncSetAttribute(k_gemm_t<true, 0, false>,
                             cudaFuncAttributeMaxDynamicSharedMemorySize, GEMM_SMEM);
        cudaFuncSetAttribute(k_gemm_t<true, 1, false>,
                             cudaFuncAttributeMaxDynamicSharedMemorySize, GEMM_SMEM);
        cudaFuncSetAttribute(k_gemm_t<false, 0, true>,
                             cudaFuncAttributeMaxDynamicSharedMemorySize, GEMM_SMEM);
        s_attr = true;
    }

    const int M = T_TOKENS;
    dim3 tgrid(128, 4, 32), tblk(32, 8);
    int lnGrid = T_TOKENS / 8;

    k_transpose<<<tgrid, tblk>>>(x, p_xr);

    // ---- block 1: W-MSA ----
    k_lnstats<<<lnGrid, 256>>>(p_xr, p_st);
    k_gemm_t<true, 0, false><<<dim3(M / 128, 3), 256, GEMM_SMEM>>>(
        p_xr, p_st, ln_g, ln_b, wq_W, wq_b, nullptr, p_qkv, M, 384, 128);
    k_attn<<<32768, 128>>>(p_qkv, wpos, p_att, 0);
    k_gemm_t<false, 0, true><<<dim3(M / 128, 1), 256, GEMM_SMEM>>>(
        p_att, nullptr, nullptr, nullptr, wp_W, wp_b, p_xr, y, M, 128, 128);
    // MLP
    k_lnstats<<<lnGrid, 256>>>(y, p_st);
    k_gemm_t<true, 1, false><<<dim3(M / 128, 4), 256, GEMM_SMEM>>>(
        y, p_st, ln_g, ln_b, m1_W, m1_b, nullptr, p_h, M, 512, 128);
    k_gemm_t<false, 0, true><<<dim3(M / 128, 1), 256, GEMM_SMEM>>>(
        p_h, nullptr, nullptr, nullptr, m2_W, m2_b, y, y, M, 128, 512);

    // ---- block 2: SW-MSA ----
    k_lnstats<<<lnGrid, 256>>>(y, p_st);
    k_gemm_t<true, 0, false><<<dim3(M / 128, 3), 256, GEMM_SMEM>>>(
        y, p_st, ln_g, ln_b, sq_W, sq_b, nullptr, p_qkv, M, 384, 128);
    k_attn<<<32768, 128>>>(p_qkv, spos, p_att, 1);
    k_gemm_t<false, 0, true><<<dim3(M / 128, 1), 256, GEMM_SMEM>>>(
        p_att, nullptr, nullptr, nullptr, sp_W, sp_b, y, y, M, 128, 128);
    // MLP
    k_lnstats<<<lnGrid, 256>>>(y, p_st);
    k_gemm_t<true, 1, false><<<dim3(M / 128, 4), 256, GEMM_SMEM>>>(
        y, p_st, ln_g, ln_b, m1_W, m1_b, nullptr, p_h, M, 512, 128);
    k_gemm_t<false, 0, true><<<dim3(M / 128, 1), 256, GEMM_SMEM>>>(
        p_h, nullptr, nullptr, nullptr, m2_W, m2_b, y, y, M, 128, 512);
}

// round 8
// speedup vs baseline: 1.3354x; 1.0120x over previous
#include <cuda_runtime.h>
#include <cuda_bf16.h>
#include <math.h>

#define T_TOKENS 131072   // 32 * 64 * 64

// ---------------- scratch (device globals, no allocation) ----------------
__device__ float          g_xr [T_TOKENS * 128];   // 64 MB
__device__ __nv_bfloat16  g_qkv[T_TOKENS * 384];   // 96 MB
__device__ float          g_att[T_TOKENS * 128];   // 64 MB
__device__ __nv_bfloat16  g_h  [T_TOKENS * 512];   // 128 MB
__device__ float2         g_st [T_TOKENS];         // 1 MB  (mu, rstd)

// ---------------- helpers ----------------
__device__ __forceinline__ unsigned f2tf32(float x) {
    unsigned r; asm("cvt.rna.tf32.f32 %0, %1;" : "=r"(r) : "f"(x)); return r;
}
__device__ __forceinline__ void mma_tf32(float c[4], const unsigned a[4], const unsigned b[2]) {
    asm volatile(
        "mma.sync.aligned.m16n8k8.row.col.f32.tf32.tf32.f32 "
        "{%0,%1,%2,%3}, {%4,%5,%6,%7}, {%8,%9}, {%0,%1,%2,%3};\n"
        : "+f"(c[0]), "+f"(c[1]), "+f"(c[2]), "+f"(c[3])
        : "r"(a[0]), "r"(a[1]), "r"(a[2]), "r"(a[3]), "r"(b[0]), "r"(b[1]));
}
__device__ __forceinline__ float gelu_exact(float x) {
    return 0.5f * x * (1.0f + erff(x * 0.70710678118654752f));
}
__device__ __forceinline__ void cp16(float* dst, const float* src) {
    unsigned s = (unsigned)__cvta_generic_to_shared(dst);
    asm volatile("cp.async.cg.shared.global [%0], [%1], 16;\n" :: "r"(s), "l"(src));
}
__device__ __forceinline__ void cp_commit() { asm volatile("cp.async.commit_group;\n"); }
__device__ __forceinline__ void cp_wait0()  { asm volatile("cp.async.wait_group 0;\n"); }

__device__ __forceinline__ void bf8_to_f8(uint4 u, float* f) {
    const __nv_bfloat162* h = (const __nv_bfloat162*)&u;
#pragma unroll
    for (int q = 0; q < 4; ++q) {
        float2 t = __bfloat1622float2(h[q]);
        f[2 * q] = t.x; f[2 * q + 1] = t.y;
    }
}

// ---------------- transpose (B,C,HW) -> (B,HW,C) ----------------
__global__ void k_transpose(const float* __restrict__ x, float* __restrict__ xr) {
    __shared__ float tile[32][33];
    int b  = blockIdx.z;
    int s0 = blockIdx.x * 32;
    int c0 = blockIdx.y * 32;
    const float* xb = x + (size_t)b * 128 * 4096;
    int tx = threadIdx.x, ty = threadIdx.y;  // 32 x 8
#pragma unroll
    for (int i = 0; i < 32; i += 8)
        tile[ty + i][tx] = xb[(size_t)(c0 + ty + i) * 4096 + s0 + tx];
    __syncthreads();
    float* xrb = xr + (size_t)b * 4096 * 128;
#pragma unroll
    for (int i = 0; i < 32; i += 8)
        xrb[(size_t)(s0 + ty + i) * 128 + c0 + tx] = tile[tx][ty + i];
}

// ---------------- LN stats: one warp per token (C=128) ----------------
__global__ void k_lnstats(const float* __restrict__ in, float2* __restrict__ st) {
    int warp = (blockIdx.x * blockDim.x + threadIdx.x) >> 5;
    int lane = threadIdx.x & 31;
    if (warp >= T_TOKENS) return;
    float4 v = ((const float4*)(in + (size_t)warp * 128))[lane];
    float s = v.x + v.y + v.z + v.w;
#pragma unroll
    for (int o = 16; o; o >>= 1) s += __shfl_xor_sync(0xffffffffu, s, o);
    float mu = s * (1.0f / 128.0f);
    float dx = v.x - mu, dy = v.y - mu, dz = v.z - mu, dw = v.w - mu;
    float q = dx * dx + dy * dy + dz * dz + dw * dw;
#pragma unroll
    for (int o = 16; o; o >>= 1) q += __shfl_xor_sync(0xffffffffu, q, o);
    float rstd = rsqrtf(q * (1.0f / 128.0f) + 1e-5f);
    if (lane == 0) { float2 o2; o2.x = mu; o2.y = rstd; st[warp] = o2; }
}

// ---------------- tf32 GEMM, 2-stage cp.async pipeline ----------------
// AMODE: 0 = fp32 A via cp.async; 1 = fp32 A with fused LN; 2 = bf16 A.
// OT: float or __nv_bfloat16 output. STATS: write per-row LN stats (requires N==128, grid.y==1).
#define GEMM_SMEM ((2 * 128 * 36 + 2 * 32 * 136) * 4)
#define AS_OFF(buf, r, c) ((buf) * (128 * 36) + (r) * 36 + (c))
#define BS_OFF(buf, r, c) (2 * 128 * 36 + (buf) * (32 * 136) + (r) * 136 + (c))

template <int AMODE, int ACT, bool RES, bool STATS, typename OT>
__global__ __launch_bounds__(256, 2)
void k_gemm_t(const void* __restrict__ Av, const float2* __restrict__ stats,
              const float* __restrict__ lng, const float* __restrict__ lnb,
              const float* __restrict__ B, const float* __restrict__ bias,
              const float* __restrict__ res, OT* __restrict__ C,
              float2* __restrict__ stout, int M, int N, int K) {
    extern __shared__ float sm[];
    const float*         Af = (const float*)Av;
    const __nv_bfloat16* Ab = (const __nv_bfloat16*)Av;

    const int tid  = threadIdx.x;
    const int lane = tid & 31;
    const int wid  = tid >> 5;
    const int wm   = (wid >> 1) * 32;
    const int wn   = (wid & 1) * 64;
    const int g    = lane >> 2;
    const int tg   = lane & 3;
    const size_t bm = (size_t)blockIdx.x * 128;
    const size_t bn = (size_t)blockIdx.y * 128;

    const int am  = tid >> 3;           // fp32 A: 0..31 row within 32-row pass
    const int ak  = (tid & 7) * 4;
    const int am2 = tid >> 2;           // bf16 A: 0..63 row within 64-row pass
    const int ak2 = (tid & 3) * 8;
    const int bk  = tid >> 5;
    const int bnn = (tid & 31) * 4;

    const float* Bg = B + (size_t)bk * N + bn + bnn;

    float2 st4[4];
    if (AMODE == 1) {
#pragma unroll
        for (int p = 0; p < 4; ++p) st4[p] = stats[bm + am + p * 32];
    }

    float acc[2][8][4];
#pragma unroll
    for (int i = 0; i < 2; ++i)
#pragma unroll
        for (int j = 0; j < 8; ++j)
#pragma unroll
            for (int r = 0; r < 4; ++r) acc[i][j][r] = 0.f;

    const int KT = K >> 5;

    // ---- prologue: tile 0 into buf 0 ----
    if (AMODE == 0) {
        const float* Ag = Af + (bm + am) * (size_t)K + ak;
#pragma unroll
        for (int p = 0; p < 4; ++p)
            cp16(&sm[AS_OFF(0, am + p * 32, ak)], Ag + (size_t)(p * 32) * K);
    } else if (AMODE == 1) {
        const float* Ag = Af + (bm + am) * (size_t)K + ak;
        float4 gv = *(const float4*)(lng + ak);
        float4 bv = *(const float4*)(lnb + ak);
#pragma unroll
        for (int p = 0; p < 4; ++p) {
            float4 av = *(const float4*)(Ag + (size_t)(p * 32) * K);
            float2 s = st4[p];
            av.x = (av.x - s.x) * s.y * gv.x + bv.x;
            av.y = (av.y - s.x) * s.y * gv.y + bv.y;
            av.z = (av.z - s.x) * s.y * gv.z + bv.z;
            av.w = (av.w - s.x) * s.y * gv.w + bv.w;
            *(float4*)&sm[AS_OFF(0, am + p * 32, ak)] = av;
        }
    } else {
        const __nv_bfloat16* Ag2 = Ab + (bm + am2) * (size_t)K + ak2;
#pragma unroll
        for (int p = 0; p < 2; ++p) {
            uint4 u = *(const uint4*)(Ag2 + (size_t)(p * 64) * K);
            float f[8]; bf8_to_f8(u, f);
            *(float4*)&sm[AS_OFF(0, am2 + p * 64, ak2)]     = *(float4*)&f[0];
            *(float4*)&sm[AS_OFF(0, am2 + p * 64, ak2 + 4)] = *(float4*)&f[4];
        }
    }
#pragma unroll
    for (int p = 0; p < 4; ++p)
        cp16(&sm[BS_OFF(0, bk + p * 8, bnn)], Bg + (size_t)(p * 8) * N);
    cp_commit();
    cp_wait0();
    __syncthreads();

    // ---- main loop: 1 sync per k-tile ----
    int buf = 0;
    for (int kt = 0; kt < KT; ++kt, buf ^= 1) {
        const bool nxt = (kt + 1 < KT);
        float4 pa[4];
        float  pa2[16];
        if (nxt) {
            const float* Bn = Bg + (size_t)(kt + 1) * 32 * N;
#pragma unroll
            for (int p = 0; p < 4; ++p)
                cp16(&sm[BS_OFF(buf ^ 1, bk + p * 8, bnn)], Bn + (size_t)(p * 8) * N);
            if (AMODE == 0) {
                const float* An = Af + (bm + am) * (size_t)K + ak + (kt + 1) * 32;
#pragma unroll
                for (int p = 0; p < 4; ++p)
                    cp16(&sm[AS_OFF(buf ^ 1, am + p * 32, ak)], An + (size_t)(p * 32) * K);
            }
            cp_commit();
            if (AMODE == 1) {
                const float* An = Af + (bm + am) * (size_t)K + ak + (kt + 1) * 32;
                float4 gv = *(const float4*)(lng + (kt + 1) * 32 + ak);
                float4 bv = *(const float4*)(lnb + (kt + 1) * 32 + ak);
#pragma unroll
                for (int p = 0; p < 4; ++p) {
                    float4 av = *(const float4*)(An + (size_t)(p * 32) * K);
                    float2 s = st4[p];
                    av.x = (av.x - s.x) * s.y * gv.x + bv.x;
                    av.y = (av.y - s.x) * s.y * gv.y + bv.y;
                    av.z = (av.z - s.x) * s.y * gv.z + bv.z;
                    av.w = (av.w - s.x) * s.y * gv.w + bv.w;
                    pa[p] = av;
                }
            } else if (AMODE == 2) {
                const __nv_bfloat16* An = Ab + (bm + am2) * (size_t)K + ak2 + (kt + 1) * 32;
#pragma unroll
                for (int p = 0; p < 2; ++p) {
                    uint4 u = *(const uint4*)(An + (size_t)(p * 64) * K);
                    bf8_to_f8(u, &pa2[p * 8]);
                }
            }
        }
        // compute on buf
#pragma unroll
        for (int ks = 0; ks < 4; ++ks) {
            const int kk = ks * 8;
            unsigned af[2][4];
#pragma unroll
            for (int mi = 0; mi < 2; ++mi) {
                const int m0 = wm + mi * 16 + g;
                af[mi][0] = f2tf32(sm[AS_OFF(buf, m0,     kk + tg)]);
                af[mi][1] = f2tf32(sm[AS_OFF(buf, m0 + 8, kk + tg)]);
                af[mi][2] = f2tf32(sm[AS_OFF(buf, m0,     kk + tg + 4)]);
                af[mi][3] = f2tf32(sm[AS_OFF(buf, m0 + 8, kk + tg + 4)]);
            }
            unsigned bf[8][2];
#pragma unroll
            for (int ni = 0; ni < 8; ++ni) {
                const int n0 = wn + ni * 8 + g;
                bf[ni][0] = f2tf32(sm[BS_OFF(buf, kk + tg,     n0)]);
                bf[ni][1] = f2tf32(sm[BS_OFF(buf, kk + tg + 4, n0)]);
            }
#pragma unroll
            for (int mi = 0; mi < 2; ++mi)
#pragma unroll
                for (int ni = 0; ni < 8; ++ni)
                    mma_tf32(acc[mi][ni], af[mi], bf[ni]);
        }
        if (nxt) {
            if (AMODE == 1) {
#pragma unroll
                for (int p = 0; p < 4; ++p)
                    *(float4*)&sm[AS_OFF(buf ^ 1, am + p * 32, ak)] = pa[p];
            } else if (AMODE == 2) {
#pragma unroll
                for (int p = 0; p < 2; ++p) {
                    *(float4*)&sm[AS_OFF(buf ^ 1, am2 + p * 64, ak2)]     = *(float4*)&pa2[p * 8];
                    *(float4*)&sm[AS_OFF(buf ^ 1, am2 + p * 64, ak2 + 4)] = *(float4*)&pa2[p * 8 + 4];
                }
            }
            cp_wait0();
            __syncthreads();
        }
    }

    // ---- epilogue ----
    float rs[4] = {0.f, 0.f, 0.f, 0.f};
    float rq[4] = {0.f, 0.f, 0.f, 0.f};
#pragma unroll
    for (int mi = 0; mi < 2; ++mi) {
        const size_t r0 = bm + wm + mi * 16 + g;
#pragma unroll
        for (int ni = 0; ni < 8; ++ni) {
            const size_t c0 = bn + wn + ni * 8 + 2 * tg;
            const float bx = bias[c0], by = bias[c0 + 1];
            float v0 = acc[mi][ni][0] + bx, v1 = acc[mi][ni][1] + by;
            float v2 = acc[mi][ni][2] + bx, v3 = acc[mi][ni][3] + by;
            if (ACT == 1) {
                v0 = gelu_exact(v0); v1 = gelu_exact(v1);
                v2 = gelu_exact(v2); v3 = gelu_exact(v3);
            }
            const size_t o0 = r0 * N + c0;
            const size_t o1 = (r0 + 8) * N + c0;
            if (RES) {
                float2 ra = *(const float2*)(res + o0);
                float2 rb = *(const float2*)(res + o1);
                v0 += ra.x; v1 += ra.y; v2 += rb.x; v3 += rb.y;
            }
            if (STATS) {
                rs[mi * 2 + 0] += v0 + v1;
                rq[mi * 2 + 0] += v0 * v0 + v1 * v1;
                rs[mi * 2 + 1] += v2 + v3;
                rq[mi * 2 + 1] += v2 * v2 + v3 * v3;
            }
            if (sizeof(OT) == 2) {
                __nv_bfloat162* Cb = (__nv_bfloat162*)C;
                Cb[o0 >> 1] = __floats2bfloat162_rn(v0, v1);
                Cb[o1 >> 1] = __floats2bfloat162_rn(v2, v3);
            } else {
                float2 w0; w0.x = v0; w0.y = v1;
                float2 w1; w1.x = v2; w1.y = v3;
                *(float2*)((float*)C + o0) = w0;
                *(float2*)((float*)C + o1) = w1;
            }
        }
    }

    if (STATS) {
        // reduce over the 4-lane tg group (lanes g*4 + tg are consecutive)
#pragma unroll
        for (int slot = 0; slot < 4; ++slot) {
#pragma unroll
            for (int o = 1; o < 4; o <<= 1) {
                rs[slot] += __shfl_xor_sync(0xffffffffu, rs[slot], o);
                rq[slot] += __shfl_xor_sync(0xffffffffu, rq[slot], o);
            }
        }
        __syncthreads();              // smem tiles no longer needed
        float2* sst = (float2*)sm;    // [128][2]
        if (tg == 0) {
#pragma unroll
            for (int slot = 0; slot < 4; ++slot) {
                int r = wm + (slot >> 1) * 16 + g + (slot & 1) * 8;
                float2 p; p.x = rs[slot]; p.y = rq[slot];
                sst[r * 2 + (wid & 1)] = p;
            }
        }
        __syncthreads();
        if (tid < 128) {
            float2 a = sst[tid * 2], b = sst[tid * 2 + 1];
            float s = a.x + b.x, q = a.y + b.y;
            float mu = s * (1.0f / 128.0f);
            float var = q * (1.0f / 128.0f) - mu * mu;
            float2 o2; o2.x = mu; o2.y = rsqrtf(var + 1e-5f);
            stout[bm + tid] = o2;
        }
    }
}

// ---------------- window attention (ws=2, n=4, heads=4, e=32), bf16 qkv in ----------------
__global__ __launch_bounds__(128)
void k_attn(const __nv_bfloat16* __restrict__ qkv, const float* __restrict__ pos,
            float* __restrict__ att, int shifted) {
    int wid = blockIdx.x;
    int ww = wid & 31, wh = (wid >> 5) & 31, b = wid >> 10;
    __shared__ float s[4][384];
    __shared__ float spos[9];
    int tid = threadIdx.x;
    if (tid < 9) spos[tid] = pos[tid];
    {
        int i = tid >> 5, lane = tid & 31;
        int lh = i >> 1, lw = i & 1;
        int h = wh * 2 + lh, w = ww * 2 + lw;
        if (shifted) { h = (h + 1) & 63; w = (w + 1) & 63; }
        size_t t = (size_t)b * 4096 + h * 64 + w;
        const __nv_bfloat162* src = (const __nv_bfloat162*)(qkv + t * 384);
#pragma unroll
        for (int j = 0; j < 6; ++j) {
            float2 v = __bfloat1622float2(src[j * 32 + lane]);
            s[i][(j * 32 + lane) * 2]     = v.x;
            s[i][(j * 32 + lane) * 2 + 1] = v.y;
        }
    }
    __syncthreads();

    int head = tid >> 5, lane = tid & 31;
    float q[4], k[4], v[4];
#pragma unroll
    for (int i = 0; i < 4; ++i) {
        int base = (lane * 4 + head) * 3;
        q[i] = s[i][base]; k[i] = s[i][base + 1]; v[i] = s[i][base + 2];
    }
    const float scale = 0.17677669529663687f;
    float sc[4][4];
#pragma unroll
    for (int i = 0; i < 4; ++i)
#pragma unroll
        for (int j = 0; j < 4; ++j) {
            float p = q[i] * k[j];
#pragma unroll
            for (int o = 16; o; o >>= 1) p += __shfl_xor_sync(0xffffffffu, p, o);
            int dx = (j >> 1) - (i >> 1) + 1;
            int dy = (j & 1) - (i & 1) + 1;
            float w = p * scale + spos[dx * 3 + dy];
            if (shifted) {
                if (wh == 31 && ((i >> 1) != (j >> 1))) w = -1e30f;
                if (ww == 31 && ((i & 1) != (j & 1))) w = -1e30f;
            }
            sc[i][j] = w;
        }
    float out[4];
#pragma unroll
    for (int i = 0; i < 4; ++i) {
        float m = fmaxf(fmaxf(sc[i][0], sc[i][1]), fmaxf(sc[i][2], sc[i][3]));
        float e0 = expf(sc[i][0] - m), e1 = expf(sc[i][1] - m);
        float e2 = expf(sc[i][2] - m), e3 = expf(sc[i][3] - m);
        float inv = 1.0f / (e0 + e1 + e2 + e3);
        out[i] = (e0 * v[0] + e1 * v[1] + e2 * v[2] + e3 * v[3]) * inv;
    }
#pragma unroll
    for (int i = 0; i < 4; ++i) {
        int lh = i >> 1, lw = i & 1;
        int h = wh * 2 + lh, w = ww * 2 + lw;
        size_t t = (size_t)b * 4096 + h * 64 + w;
        att[t * 128 + head * 32 + lane] = out[i];
    }
}

// ---------------- host orchestration ----------------
extern "C" void kernel_launch(void* const* d_in, const int* in_sizes, int n_in,
                              void* d_out, int out_size) {
    const float* x    = (const float*)d_in[0];
    const float* ln_g = (const float*)d_in[1];
    const float* ln_b = (const float*)d_in[2];
    const float* wq_W = (const float*)d_in[3];
    const float* wq_b = (const float*)d_in[4];
    const float* wp_W = (const float*)d_in[5];
    const float* wp_b = (const float*)d_in[6];
    const float* wpos = (const float*)d_in[7];
    const float* sq_W = (const float*)d_in[8];
    const float* sq_b = (const float*)d_in[9];
    const float* sp_W = (const float*)d_in[10];
    const float* sp_b = (const float*)d_in[11];
    const float* spos = (const float*)d_in[12];
    const float* m1_W = (const float*)d_in[13];
    const float* m1_b = (const float*)d_in[14];
    const float* m2_W = (const float*)d_in[15];
    const float* m2_b = (const float*)d_in[16];
    float* y = (float*)d_out;

    float *p_xr, *p_att;
    __nv_bfloat16 *p_qkv, *p_h;
    float2* p_st;
    cudaGetSymbolAddress((void**)&p_xr,  g_xr);
    cudaGetSymbolAddress((void**)&p_qkv, g_qkv);
    cudaGetSymbolAddress((void**)&p_att, g_att);
    cudaGetSymbolAddress((void**)&p_h,   g_h);
    cudaGetSymbolAddress((void**)&p_st,  g_st);

    static bool s_attr = false;
    if (!s_attr) {
        cudaFuncSetAttribute(k_gemm_t<1, 0, false, false, __nv_bfloat16>,
                             cudaFuncAttributeMaxDynamicSharedMemorySize, GEMM_SMEM);
        cudaFuncSetAttribute(k_gemm_t<0, 0, true, true, float>,
                             cudaFuncAttributeMaxDynamicSharedMemorySize, GEMM_SMEM);
        cudaFuncSetAttribute(k_gemm_t<1, 1, false, false, __nv_bfloat16>,
                             cudaFuncAttributeMaxDynamicSharedMemorySize, GEMM_SMEM);
        cudaFuncSetAttribute(k_gemm_t<2, 0, true, true, float>,
                             cudaFuncAttributeMaxDynamicSharedMemorySize, GEMM_SMEM);
        s_attr = true;
    }

    const int M = T_TOKENS;
    dim3 tgrid(128, 4, 32), tblk(32, 8);

    k_transpose<<<tgrid, tblk>>>(x, p_xr);
    k_lnstats<<<T_TOKENS / 8, 256>>>(p_xr, p_st);

    // ---- block 1: W-MSA ----
    k_gemm_t<1, 0, false, false, __nv_bfloat16><<<dim3(M / 128, 3), 256, GEMM_SMEM>>>(
        p_xr, p_st, ln_g, ln_b, wq_W, wq_b, nullptr, p_qkv, nullptr, M, 384, 128);
    k_attn<<<32768, 128>>>(p_qkv, wpos, p_att, 0);
    k_gemm_t<0, 0, true, true, float><<<dim3(M / 128, 1), 256, GEMM_SMEM>>>(
        p_att, nullptr, nullptr, nullptr, wp_W, wp_b, p_xr, y, p_st, M, 128, 128);
    // MLP (stats for next LN come from proj epilogue)
    k_gemm_t<1, 1, false, false, __nv_bfloat16><<<dim3(M / 128, 4), 256, GEMM_SMEM>>>(
        y, p_st, ln_g, ln_b, m1_W, m1_b, nullptr, p_h, nullptr, M, 512, 128);
    k_gemm_t<2, 0, true, true, float><<<dim3(M / 128, 1), 256, GEMM_SMEM>>>(
        p_h, nullptr, nullptr, nullptr, m2_W, m2_b, y, y, p_st, M, 128, 512);

    // ---- block 2: SW-MSA (stats from MLP2 epilogue) ----
    k_gemm_t<1, 0, false, false, __nv_bfloat16><<<dim3(M / 128, 3), 256, GEMM_SMEM>>>(
        y, p_st, ln_g, ln_b, sq_W, sq_b, nullptr, p_qkv, nullptr, M, 384, 128);
    k_attn<<<32768, 128>>>(p_qkv, spos, p_att, 1);
    k_gemm_t<0, 0, true, true, float><<<dim3(M / 128, 1), 256, GEMM_SMEM>>>(
        p_att, nullptr, nullptr, nullptr, sp_W, sp_b, y, y, p_st, M, 128, 128);
    // MLP
    k_gemm_t<1, 1, false, false, __nv_bfloat16><<<dim3(M / 128, 4), 256, GEMM_SMEM>>>(
        y, p_st, ln_g, ln_b, m1_W, m1_b, nullptr, p_h, nullptr, M, 512, 128);
    k_gemm_t<2, 0, true, true, float><<<dim3(M / 128, 1), 256, GEMM_SMEM>>>(
        p_h, nullptr, nullptr, nullptr, m2_W, m2_b, y, y, p_st, M, 128, 512);
}

// round 9
// speedup vs baseline: 1.4928x; 1.1179x over previous
#include <cuda_runtime.h>
#include <cuda_bf16.h>
#include <math.h>

#define T_TOKENS 131072   // 32 * 64 * 64

// ---------------- scratch (device globals, no allocation) ----------------
__device__ float          g_xr [T_TOKENS * 128];   // 64 MB
__device__ __nv_bfloat16  g_qkv[T_TOKENS * 384];   // 96 MB
__device__ __nv_bfloat16  g_att[T_TOKENS * 128];   // 32 MB
__device__ __nv_bfloat16  g_h  [T_TOKENS * 512];   // 128 MB
__device__ float2         g_st [T_TOKENS];         // 1 MB  (mu, rstd)
__device__ __nv_bfloat16  g_wb [262144];           // bf16 weight pool (512 KB)

// weight pool offsets
#define W_WQ 0
#define W_WP 49152
#define W_M1 65536
#define W_M2 131072
#define W_SQ 196608
#define W_SP 245760

// ---------------- helpers ----------------
__device__ __forceinline__ void mma_bf16(float c[4], const unsigned a[4], const unsigned b0, const unsigned b1) {
    asm volatile(
        "mma.sync.aligned.m16n8k16.row.col.f32.bf16.bf16.f32 "
        "{%0,%1,%2,%3}, {%4,%5,%6,%7}, {%8,%9}, {%0,%1,%2,%3};\n"
        : "+f"(c[0]), "+f"(c[1]), "+f"(c[2]), "+f"(c[3])
        : "r"(a[0]), "r"(a[1]), "r"(a[2]), "r"(a[3]), "r"(b0), "r"(b1));
}
__device__ __forceinline__ void ldsm4(unsigned r[4], unsigned addr) {
    asm volatile("ldmatrix.sync.aligned.m8n8.x4.shared.b16 {%0,%1,%2,%3}, [%4];"
        : "=r"(r[0]), "=r"(r[1]), "=r"(r[2]), "=r"(r[3]) : "r"(addr));
}
__device__ __forceinline__ void ldsm4t(unsigned r[4], unsigned addr) {
    asm volatile("ldmatrix.sync.aligned.m8n8.x4.trans.shared.b16 {%0,%1,%2,%3}, [%4];"
        : "=r"(r[0]), "=r"(r[1]), "=r"(r[2]), "=r"(r[3]) : "r"(addr));
}
__device__ __forceinline__ float gelu_exact(float x) {
    return 0.5f * x * (1.0f + erff(x * 0.70710678118654752f));
}
__device__ __forceinline__ void cp16b(__nv_bfloat16* dst, const __nv_bfloat16* src) {
    unsigned s = (unsigned)__cvta_generic_to_shared(dst);
    asm volatile("cp.async.cg.shared.global [%0], [%1], 16;\n" :: "r"(s), "l"(src));
}
__device__ __forceinline__ void cp_commit() { asm volatile("cp.async.commit_group;\n"); }
__device__ __forceinline__ void cp_wait0()  { asm volatile("cp.async.wait_group 0;\n"); }

__device__ __forceinline__ uint4 pack8(const float* f) {
    uint4 u; __nv_bfloat162* p = (__nv_bfloat162*)&u;
#pragma unroll
    for (int j = 0; j < 4; ++j) p[j] = __floats2bfloat162_rn(f[2 * j], f[2 * j + 1]);
    return u;
}

// ---------------- weight pool conversion (fp32 -> bf16), runs each launch ----------------
__global__ void k_wconv(const float* __restrict__ wq, const float* __restrict__ wp,
                        const float* __restrict__ m1, const float* __restrict__ m2,
                        const float* __restrict__ sq, const float* __restrict__ sp,
                        __nv_bfloat16* __restrict__ out) {
    int idx = (blockIdx.x * blockDim.x + threadIdx.x) * 4;   // 65536 threads x 4
    const float* src; int base;
    if      (idx < W_WP) { src = wq; base = W_WQ; }
    else if (idx < W_M1) { src = wp; base = W_WP; }
    else if (idx < W_M2) { src = m1; base = W_M1; }
    else if (idx < W_SQ) { src = m2; base = W_M2; }
    else if (idx < W_SP) { src = sq; base = W_SQ; }
    else                 { src = sp; base = W_SP; }
    float4 v = *(const float4*)(src + (idx - base));
    *(__nv_bfloat162*)(out + idx)     = __floats2bfloat162_rn(v.x, v.y);
    *(__nv_bfloat162*)(out + idx + 2) = __floats2bfloat162_rn(v.z, v.w);
}

// ---------------- transpose (B,C,HW) -> (B,HW,C) ----------------
__global__ void k_transpose(const float* __restrict__ x, float* __restrict__ xr) {
    __shared__ float tile[32][33];
    int b  = blockIdx.z;
    int s0 = blockIdx.x * 32;
    int c0 = blockIdx.y * 32;
    const float* xb = x + (size_t)b * 128 * 4096;
    int tx = threadIdx.x, ty = threadIdx.y;  // 32 x 8
#pragma unroll
    for (int i = 0; i < 32; i += 8)
        tile[ty + i][tx] = xb[(size_t)(c0 + ty + i) * 4096 + s0 + tx];
    __syncthreads();
    float* xrb = xr + (size_t)b * 4096 * 128;
#pragma unroll
    for (int i = 0; i < 32; i += 8)
        xrb[(size_t)(s0 + ty + i) * 128 + c0 + tx] = tile[tx][ty + i];
}

// ---------------- LN stats: one warp per token (C=128) ----------------
__global__ void k_lnstats(const float* __restrict__ in, float2* __restrict__ st) {
    int warp = (blockIdx.x * blockDim.x + threadIdx.x) >> 5;
    int lane = threadIdx.x & 31;
    if (warp >= T_TOKENS) return;
    float4 v = ((const float4*)(in + (size_t)warp * 128))[lane];
    float s = v.x + v.y + v.z + v.w;
#pragma unroll
    for (int o = 16; o; o >>= 1) s += __shfl_xor_sync(0xffffffffu, s, o);
    float mu = s * (1.0f / 128.0f);
    float dx = v.x - mu, dy = v.y - mu, dz = v.z - mu, dw = v.w - mu;
    float q = dx * dx + dy * dy + dz * dz + dw * dw;
#pragma unroll
    for (int o = 16; o; o >>= 1) q += __shfl_xor_sync(0xffffffffu, q, o);
    float rstd = rsqrtf(q * (1.0f / 128.0f) + 1e-5f);
    if (lane == 0) { float2 o2; o2.x = mu; o2.y = rstd; st[warp] = o2; }
}

// ---------------- bf16 tensor-core GEMM, 2-stage cp.async pipeline ----------------
// AMODE: 1 = fp32 A with fused LN (reg-staged, bf16 STS); 2 = bf16 A via cp.async.
// B is bf16 (weight pool). BM=BN=128, BK=32, 256 threads, warp tile 32x64, mma.m16n8k16.
// smem (bf16): As[2][128][40] + Bs[2][32][136] = 37888 B (static).
#define SA 40
#define SB 136
#define A_BYTES (128 * SA * 2)      // 10240
#define B_BYTES (32 * SB * 2)       // 8704

template <int AMODE, int ACT, bool RES, bool STATS, typename OT>
__global__ __launch_bounds__(256, 2)
void k_gemm_b(const void* __restrict__ Av, const float2* __restrict__ stats,
              const float* __restrict__ lng, const float* __restrict__ lnb,
              const __nv_bfloat16* __restrict__ Bb, const float* __restrict__ bias,
              const float* __restrict__ res, OT* __restrict__ C,
              float2* __restrict__ stout, int M, int N, int K) {
    __shared__ __nv_bfloat16 smem[2 * 128 * SA + 2 * 32 * SB];
    const float*         Af = (const float*)Av;
    const __nv_bfloat16* Ab = (const __nv_bfloat16*)Av;
    const unsigned smbase = (unsigned)__cvta_generic_to_shared(smem);

    const int tid  = threadIdx.x;
    const int lane = tid & 31;
    const int wid  = tid >> 5;
    const int wm   = (wid >> 1) * 32;
    const int wn   = (wid & 1) * 64;
    const int g    = lane >> 2;
    const int tg   = lane & 3;
    const size_t bm = (size_t)blockIdx.x * 128;
    const size_t bn = (size_t)blockIdx.y * 128;

    // stage mapping: A row + k-half per thread
    const int ar = tid & 127;
    const int ah = (tid >> 7) * 16;
    // B: row + 16-col chunk
    const int br = tid >> 3;
    const int bc = (tid & 7) * 16;

    const __nv_bfloat16* Bg = Bb + (size_t)br * N + bn + bc;

    // ldmatrix per-lane address components (bytes, relative to smem base)
    const int lq = lane & 7, lh = (lane >> 3) & 1, lt = lane >> 4;
    const unsigned aRC = (unsigned)(((wm + lq + lh * 8) * SA + lt * 8) * 2);
    const unsigned bRC = (unsigned)(2 * 128 * SA * 2 /*bytes offset of B region*/) / 2 * 0 +
                         (unsigned)((2 * 128 * SA) * 2) * 0; // (computed below)
    const unsigned bReg = (unsigned)(2 * 128 * SA * 2);      // byte offset where B buffers start
    const unsigned bRC2 = bReg + (unsigned)(((lq + lh * 8) * SB + wn + lt * 8) * 2);

    float2 stA;
    if (AMODE == 1) stA = stats[bm + ar];

    float acc[2][8][4];
#pragma unroll
    for (int i = 0; i < 2; ++i)
#pragma unroll
        for (int j = 0; j < 8; ++j)
#pragma unroll
            for (int r = 0; r < 4; ++r) acc[i][j][r] = 0.f;

    const int KT = K >> 5;
    const float* Afr = Af + (bm + ar) * (size_t)K + ah;
    const __nv_bfloat16* Abr = Ab + (bm + ar) * (size_t)K + ah;

    // ---- prologue: tile 0 into buf 0 ----
    if (AMODE == 1) {
        float f[16];
#pragma unroll
        for (int j = 0; j < 4; ++j) {
            float4 v  = *(const float4*)(Afr + j * 4);
            float4 gv = *(const float4*)(lng + ah + j * 4);
            float4 bv = *(const float4*)(lnb + ah + j * 4);
            f[4*j+0] = (v.x - stA.x) * stA.y * gv.x + bv.x;
            f[4*j+1] = (v.y - stA.x) * stA.y * gv.y + bv.y;
            f[4*j+2] = (v.z - stA.x) * stA.y * gv.z + bv.z;
            f[4*j+3] = (v.w - stA.x) * stA.y * gv.w + bv.w;
        }
        *(uint4*)&smem[ar * SA + ah]     = pack8(f);
        *(uint4*)&smem[ar * SA + ah + 8] = pack8(f + 8);
    } else {
        cp16b(&smem[ar * SA + ah],     Abr);
        cp16b(&smem[ar * SA + ah + 8], Abr + 8);
    }
    {
        __nv_bfloat16* bdst = smem + 2 * 128 * SA + br * SB + bc;
        cp16b(bdst,     Bg);
        cp16b(bdst + 8, Bg + 8);
    }
    cp_commit();
    cp_wait0();
    __syncthreads();

    // ---- main loop ----
    int buf = 0;
    for (int kt = 0; kt < KT; ++kt, buf ^= 1) {
        const bool nxt = (kt + 1 < KT);
        float4 pv[4];
        if (nxt) {
            const __nv_bfloat16* Bn = Bg + (size_t)(kt + 1) * 32 * N;
            __nv_bfloat16* bdst = smem + 2 * 128 * SA + (buf ^ 1) * 32 * SB + br * SB + bc;
            cp16b(bdst,     Bn);
            cp16b(bdst + 8, Bn + 8);
            if (AMODE == 2) {
                const __nv_bfloat16* An = Abr + (kt + 1) * 32;
                __nv_bfloat16* adst = smem + (buf ^ 1) * 128 * SA + ar * SA + ah;
                cp16b(adst,     An);
                cp16b(adst + 8, An + 8);
            }
            cp_commit();
            if (AMODE == 1) {
                const float* An = Afr + (kt + 1) * 32;
#pragma unroll
                for (int j = 0; j < 4; ++j) pv[j] = *(const float4*)(An + j * 4);
            }
        }

        // compute on buf
        const unsigned aBase = smbase + (unsigned)(buf * A_BYTES) + aRC;
        const unsigned bBase = smbase + (unsigned)(buf * B_BYTES) + bRC2;
#pragma unroll
        for (int ks = 0; ks < 2; ++ks) {
            const unsigned kA = (unsigned)(ks * 16 * 2);          // +16 bf16 cols
            const unsigned kB = (unsigned)(ks * 16 * SB * 2);     // +16 k-rows
            unsigned af[2][4];
            ldsm4(af[0], aBase + kA);
            ldsm4(af[1], aBase + kA + (unsigned)(16 * SA * 2));
            unsigned bfr[4][4];
#pragma unroll
            for (int p = 0; p < 4; ++p)
                ldsm4t(bfr[p], bBase + kB + (unsigned)(p * 16 * 2));
#pragma unroll
            for (int mi = 0; mi < 2; ++mi)
#pragma unroll
                for (int p = 0; p < 4; ++p) {
                    mma_bf16(acc[mi][2 * p],     af[mi], bfr[p][0], bfr[p][1]);
                    mma_bf16(acc[mi][2 * p + 1], af[mi], bfr[p][2], bfr[p][3]);
                }
        }

        if (nxt) {
            if (AMODE == 1) {
                float f[16];
#pragma unroll
                for (int j = 0; j < 4; ++j) {
                    float4 gv = *(const float4*)(lng + (kt + 1) * 32 + ah + j * 4);
                    float4 bv = *(const float4*)(lnb + (kt + 1) * 32 + ah + j * 4);
                    f[4*j+0] = (pv[j].x - stA.x) * stA.y * gv.x + bv.x;
                    f[4*j+1] = (pv[j].y - stA.x) * stA.y * gv.y + bv.y;
                    f[4*j+2] = (pv[j].z - stA.x) * stA.y * gv.z + bv.z;
                    f[4*j+3] = (pv[j].w - stA.x) * stA.y * gv.w + bv.w;
                }
                __nv_bfloat16* adst = smem + (buf ^ 1) * 128 * SA + ar * SA + ah;
                *(uint4*)adst       = pack8(f);
                *(uint4*)(adst + 8) = pack8(f + 8);
            }
            cp_wait0();
            __syncthreads();
        }
    }

    // ---- epilogue ----
    float rs[4] = {0.f, 0.f, 0.f, 0.f};
    float rq[4] = {0.f, 0.f, 0.f, 0.f};
#pragma unroll
    for (int mi = 0; mi < 2; ++mi) {
        const size_t r0 = bm + wm + mi * 16 + g;
#pragma unroll
        for (int ni = 0; ni < 8; ++ni) {
            const size_t c0 = bn + wn + ni * 8 + 2 * tg;
            const float bx = bias[c0], by = bias[c0 + 1];
            float v0 = acc[mi][ni][0] + bx, v1 = acc[mi][ni][1] + by;
            float v2 = acc[mi][ni][2] + bx, v3 = acc[mi][ni][3] + by;
            if (ACT == 1) {
                v0 = gelu_exact(v0); v1 = gelu_exact(v1);
                v2 = gelu_exact(v2); v3 = gelu_exact(v3);
            }
            const size_t o0 = r0 * N + c0;
            const size_t o1 = (r0 + 8) * N + c0;
            if (RES) {
                float2 ra = *(const float2*)(res + o0);
                float2 rb = *(const float2*)(res + o1);
                v0 += ra.x; v1 += ra.y; v2 += rb.x; v3 += rb.y;
            }
            if (STATS) {
                rs[mi * 2 + 0] += v0 + v1;
                rq[mi * 2 + 0] += v0 * v0 + v1 * v1;
                rs[mi * 2 + 1] += v2 + v3;
                rq[mi * 2 + 1] += v2 * v2 + v3 * v3;
            }
            if (sizeof(OT) == 2) {
                __nv_bfloat162* Cb = (__nv_bfloat162*)C;
                Cb[o0 >> 1] = __floats2bfloat162_rn(v0, v1);
                Cb[o1 >> 1] = __floats2bfloat162_rn(v2, v3);
            } else {
                float2 w0; w0.x = v0; w0.y = v1;
                float2 w1; w1.x = v2; w1.y = v3;
                *(float2*)((float*)C + o0) = w0;
                *(float2*)((float*)C + o1) = w1;
            }
        }
    }

    if (STATS) {
#pragma unroll
        for (int slot = 0; slot < 4; ++slot) {
#pragma unroll
            for (int o = 1; o < 4; o <<= 1) {
                rs[slot] += __shfl_xor_sync(0xffffffffu, rs[slot], o);
                rq[slot] += __shfl_xor_sync(0xffffffffu, rq[slot], o);
            }
        }
        __syncthreads();
        float2* sst = (float2*)smem;    // [128][2]
        if (tg == 0) {
#pragma unroll
            for (int slot = 0; slot < 4; ++slot) {
                int r = wm + (slot >> 1) * 16 + g + (slot & 1) * 8;
                float2 p; p.x = rs[slot]; p.y = rq[slot];
                sst[r * 2 + (wid & 1)] = p;
            }
        }
        __syncthreads();
        if (tid < 128) {
            float2 a = sst[tid * 2], b = sst[tid * 2 + 1];
            float s = a.x + b.x, q = a.y + b.y;
            float mu = s * (1.0f / 128.0f);
            float var = q * (1.0f / 128.0f) - mu * mu;
            float2 o2; o2.x = mu; o2.y = rsqrtf(var + 1e-5f);
            stout[bm + tid] = o2;
        }
    }
}

// ---------------- window attention (ws=2, n=4, heads=4, e=32), bf16 in/out ----------------
__global__ __launch_bounds__(128)
void k_attn(const __nv_bfloat16* __restrict__ qkv, const float* __restrict__ pos,
            __nv_bfloat16* __restrict__ att, int shifted) {
    int wid = blockIdx.x;
    int ww = wid & 31, wh = (wid >> 5) & 31, b = wid >> 10;
    __shared__ float s[4][384];
    __shared__ float spos[9];
    int tid = threadIdx.x;
    if (tid < 9) spos[tid] = pos[tid];
    {
        int i = tid >> 5, lane = tid & 31;
        int lh = i >> 1, lw = i & 1;
        int h = wh * 2 + lh, w = ww * 2 + lw;
        if (shifted) { h = (h + 1) & 63; w = (w + 1) & 63; }
        size_t t = (size_t)b * 4096 + h * 64 + w;
        const __nv_bfloat162* src = (const __nv_bfloat162*)(qkv + t * 384);
#pragma unroll
        for (int j = 0; j < 6; ++j) {
            float2 v = __bfloat1622float2(src[j * 32 + lane]);
            s[i][(j * 32 + lane) * 2]     = v.x;
            s[i][(j * 32 + lane) * 2 + 1] = v.y;
        }
    }
    __syncthreads();

    int head = tid >> 5, lane = tid & 31;
    float q[4], k[4], v[4];
#pragma unroll
    for (int i = 0; i < 4; ++i) {
        int base = (lane * 4 + head) * 3;
        q[i] = s[i][base]; k[i] = s[i][base + 1]; v[i] = s[i][base + 2];
    }
    const float scale = 0.17677669529663687f;
    float sc[4][4];
#pragma unroll
    for (int i = 0; i < 4; ++i)
#pragma unroll
        for (int j = 0; j < 4; ++j) {
            float p = q[i] * k[j];
#pragma unroll
            for (int o = 16; o; o >>= 1) p += __shfl_xor_sync(0xffffffffu, p, o);
            int dx = (j >> 1) - (i >> 1) + 1;
            int dy = (j & 1) - (i & 1) + 1;
            float w = p * scale + spos[dx * 3 + dy];
            if (shifted) {
                if (wh == 31 && ((i >> 1) != (j >> 1))) w = -1e30f;
                if (ww == 31 && ((i & 1) != (j & 1))) w = -1e30f;
            }
            sc[i][j] = w;
        }
    float out[4];
#pragma unroll
    for (int i = 0; i < 4; ++i) {
        float m = fmaxf(fmaxf(sc[i][0], sc[i][1]), fmaxf(sc[i][2], sc[i][3]));
        float e0 = expf(sc[i][0] - m), e1 = expf(sc[i][1] - m);
        float e2 = expf(sc[i][2] - m), e3 = expf(sc[i][3] - m);
        float inv = 1.0f / (e0 + e1 + e2 + e3);
        out[i] = (e0 * v[0] + e1 * v[1] + e2 * v[2] + e3 * v[3]) * inv;
    }
#pragma unroll
    for (int i = 0; i < 4; ++i) {
        int lh = i >> 1, lw = i & 1;
        int h = wh * 2 + lh, w = ww * 2 + lw;
        size_t t = (size_t)b * 4096 + h * 64 + w;
        att[t * 128 + head * 32 + lane] = __float2bfloat16(out[i]);
    }
}

// ---------------- host orchestration ----------------
extern "C" void kernel_launch(void* const* d_in, const int* in_sizes, int n_in,
                              void* d_out, int out_size) {
    const float* x    = (const float*)d_in[0];
    const float* ln_g = (const float*)d_in[1];
    const float* ln_b = (const float*)d_in[2];
    const float* wq_W = (const float*)d_in[3];
    const float* wq_b = (const float*)d_in[4];
    const float* wp_W = (const float*)d_in[5];
    const float* wp_b = (const float*)d_in[6];
    const float* wpos = (const float*)d_in[7];
    const float* sq_W = (const float*)d_in[8];
    const float* sq_b = (const float*)d_in[9];
    const float* sp_W = (const float*)d_in[10];
    const float* sp_b = (const float*)d_in[11];
    const float* spos = (const float*)d_in[12];
    const float* m1_W = (const float*)d_in[13];
    const float* m1_b = (const float*)d_in[14];
    const float* m2_W = (const float*)d_in[15];
    const float* m2_b = (const float*)d_in[16];
    float* y = (float*)d_out;

    float* p_xr;
    __nv_bfloat16 *p_qkv, *p_att, *p_h, *p_wb;
    float2* p_st;
    cudaGetSymbolAddress((void**)&p_xr,  g_xr);
    cudaGetSymbolAddress((void**)&p_qkv, g_qkv);
    cudaGetSymbolAddress((void**)&p_att, g_att);
    cudaGetSymbolAddress((void**)&p_h,   g_h);
    cudaGetSymbolAddress((void**)&p_st,  g_st);
    cudaGetSymbolAddress((void**)&p_wb,  g_wb);

    const int M = T_TOKENS;
    dim3 tgrid(128, 4, 32), tblk(32, 8);

    k_wconv<<<256, 256>>>(wq_W, wp_W, m1_W, m2_W, sq_W, sp_W, p_wb);
    k_transpose<<<tgrid, tblk>>>(x, p_xr);
    k_lnstats<<<T_TOKENS / 8, 256>>>(p_xr, p_st);

    // ---- block 1: W-MSA ----
    k_gemm_b<1, 0, false, false, __nv_bfloat16><<<dim3(M / 128, 3), 256>>>(
        p_xr, p_st, ln_g, ln_b, p_wb + W_WQ, wq_b, nullptr, p_qkv, nullptr, M, 384, 128);
    k_attn<<<32768, 128>>>(p_qkv, wpos, p_att, 0);
    k_gemm_b<2, 0, true, true, float><<<dim3(M / 128, 1), 256>>>(
        p_att, nullptr, nullptr, nullptr, p_wb + W_WP, wp_b, p_xr, y, p_st, M, 128, 128);
    // MLP (stats from proj epilogue)
    k_gemm_b<1, 1, false, false, __nv_bfloat16><<<dim3(M / 128, 4), 256>>>(
        y, p_st, ln_g, ln_b, p_wb + W_M1, m1_b, nullptr, p_h, nullptr, M, 512, 128);
    k_gemm_b<2, 0, true, true, float><<<dim3(M / 128, 1), 256>>>(
        p_h, nullptr, nullptr, nullptr, p_wb + W_M2, m2_b, y, y, p_st, M, 128, 512);

    // ---- block 2: SW-MSA (stats from MLP2 epilogue) ----
    k_gemm_b<1, 0, false, false, __nv_bfloat16><<<dim3(M / 128, 3), 256>>>(
        y, p_st, ln_g, ln_b, p_wb + W_SQ, sq_b, nullptr, p_qkv, nullptr, M, 384, 128);
    k_attn<<<32768, 128>>>(p_qkv, spos, p_att, 1);
    k_gemm_b<2, 0, true, true, float><<<dim3(M / 128, 1), 256>>>(
        p_att, nullptr, nullptr, nullptr, p_wb + W_SP, sp_b, y, y, p_st, M, 128, 128);
    // MLP
    k_gemm_b<1, 1, false, false, __nv_bfloat16><<<dim3(M / 128, 4), 256>>>(
        y, p_st, ln_g, ln_b, p_wb + W_M1, m1_b, nullptr, p_h, nullptr, M, 512, 128);
    k_gemm_b<2, 0, true, true, float><<<dim3(M / 128, 1), 256>>>(
        p_h, nullptr, nullptr, nullptr, p_wb + W_M2, m2_b, y, y, p_st, M, 128, 512);
}

// round 10
// speedup vs baseline: 1.8017x; 1.2070x over previous
#include <cuda_runtime.h>
#include <cuda_bf16.h>
#include <math.h>

#define T_TOKENS 131072   // 32 * 64 * 64

// ---------------- scratch (device globals, no allocation) ----------------
__device__ float          g_xr [T_TOKENS * 128];   // 64 MB (fp32 residual base)
__device__ __nv_bfloat16  g_ln [T_TOKENS * 128];   // 32 MB (bf16 LN'd activations)
__device__ __nv_bfloat16  g_qkv[T_TOKENS * 384];   // 96 MB
__device__ __nv_bfloat16  g_att[T_TOKENS * 128];   // 32 MB
__device__ __nv_bfloat16  g_h  [T_TOKENS * 512];   // 128 MB
__device__ __nv_bfloat16  g_wb [262144];           // bf16 weight pool (512 KB)

// weight pool offsets
#define W_WQ 0
#define W_WP 49152
#define W_M1 65536
#define W_M2 131072
#define W_SQ 196608
#define W_SP 245760

// ---------------- helpers ----------------
__device__ __forceinline__ void mma_bf16(float c[4], const unsigned a[4], const unsigned b0, const unsigned b1) {
    asm volatile(
        "mma.sync.aligned.m16n8k16.row.col.f32.bf16.bf16.f32 "
        "{%0,%1,%2,%3}, {%4,%5,%6,%7}, {%8,%9}, {%0,%1,%2,%3};\n"
        : "+f"(c[0]), "+f"(c[1]), "+f"(c[2]), "+f"(c[3])
        : "r"(a[0]), "r"(a[1]), "r"(a[2]), "r"(a[3]), "r"(b0), "r"(b1));
}
__device__ __forceinline__ void ldsm4(unsigned r[4], unsigned addr) {
    asm volatile("ldmatrix.sync.aligned.m8n8.x4.shared.b16 {%0,%1,%2,%3}, [%4];"
        : "=r"(r[0]), "=r"(r[1]), "=r"(r[2]), "=r"(r[3]) : "r"(addr));
}
__device__ __forceinline__ void ldsm4t(unsigned r[4], unsigned addr) {
    asm volatile("ldmatrix.sync.aligned.m8n8.x4.trans.shared.b16 {%0,%1,%2,%3}, [%4];"
        : "=r"(r[0]), "=r"(r[1]), "=r"(r[2]), "=r"(r[3]) : "r"(addr));
}
__device__ __forceinline__ float gelu_exact(float x) {
    return 0.5f * x * (1.0f + erff(x * 0.70710678118654752f));
}
__device__ __forceinline__ void cp16b(__nv_bfloat16* dst, const __nv_bfloat16* src) {
    unsigned s = (unsigned)__cvta_generic_to_shared(dst);
    asm volatile("cp.async.cg.shared.global [%0], [%1], 16;\n" :: "r"(s), "l"(src));
}
__device__ __forceinline__ void cp_commit() { asm volatile("cp.async.commit_group;\n"); }
__device__ __forceinline__ void cp_wait_n(int n) {
    if (n == 0)      asm volatile("cp.async.wait_group 0;\n");
    else if (n == 1) asm volatile("cp.async.wait_group 1;\n");
    else             asm volatile("cp.async.wait_group 2;\n");
}

// ---------------- weight pool conversion (fp32 -> bf16) ----------------
__global__ void k_wconv(const float* __restrict__ wq, const float* __restrict__ wp,
                        const float* __restrict__ m1, const float* __restrict__ m2,
                        const float* __restrict__ sq, const float* __restrict__ sp,
                        __nv_bfloat16* __restrict__ out) {
    int idx = (blockIdx.x * blockDim.x + threadIdx.x) * 4;
    const float* src; int base;
    if      (idx < W_WP) { src = wq; base = W_WQ; }
    else if (idx < W_M1) { src = wp; base = W_WP; }
    else if (idx < W_M2) { src = m1; base = W_M1; }
    else if (idx < W_SQ) { src = m2; base = W_M2; }
    else if (idx < W_SP) { src = sq; base = W_SQ; }
    else                 { src = sp; base = W_SP; }
    float4 v = *(const float4*)(src + (idx - base));
    *(__nv_bfloat162*)(out + idx)     = __floats2bfloat162_rn(v.x, v.y);
    *(__nv_bfloat162*)(out + idx + 2) = __floats2bfloat162_rn(v.z, v.w);
}

// ---------------- transpose (B,C,HW) -> (B,HW,C) ----------------
__global__ void k_transpose(const float* __restrict__ x, float* __restrict__ xr) {
    __shared__ float tile[32][33];
    int b  = blockIdx.z;
    int s0 = blockIdx.x * 32;
    int c0 = blockIdx.y * 32;
    const float* xb = x + (size_t)b * 128 * 4096;
    int tx = threadIdx.x, ty = threadIdx.y;  // 32 x 8
#pragma unroll
    for (int i = 0; i < 32; i += 8)
        tile[ty + i][tx] = xb[(size_t)(c0 + ty + i) * 4096 + s0 + tx];
    __syncthreads();
    float* xrb = xr + (size_t)b * 4096 * 128;
#pragma unroll
    for (int i = 0; i < 32; i += 8)
        xrb[(size_t)(s0 + ty + i) * 128 + c0 + tx] = tile[tx][ty + i];
}

// ---------------- LN (fp32 in -> bf16 out), one warp per token ----------------
__global__ void k_ln_bf16(const float* __restrict__ in, const float* __restrict__ g,
                          const float* __restrict__ bta, __nv_bfloat16* __restrict__ out) {
    int warp = (blockIdx.x * blockDim.x + threadIdx.x) >> 5;
    int lane = threadIdx.x & 31;
    if (warp >= T_TOKENS) return;
    float4 v = ((const float4*)(in + (size_t)warp * 128))[lane];
    float s = v.x + v.y + v.z + v.w;
#pragma unroll
    for (int o = 16; o; o >>= 1) s += __shfl_xor_sync(0xffffffffu, s, o);
    float mu = s * (1.0f / 128.0f);
    float dx = v.x - mu, dy = v.y - mu, dz = v.z - mu, dw = v.w - mu;
    float q = dx * dx + dy * dy + dz * dz + dw * dw;
#pragma unroll
    for (int o = 16; o; o >>= 1) q += __shfl_xor_sync(0xffffffffu, q, o);
    float rstd = rsqrtf(q * (1.0f / 128.0f) + 1e-5f);
    float4 gv = ((const float4*)g)[lane];
    float4 bv = ((const float4*)bta)[lane];
    uint2 o2;
    ((__nv_bfloat162*)&o2)[0] = __floats2bfloat162_rn(dx * rstd * gv.x + bv.x, dy * rstd * gv.y + bv.y);
    ((__nv_bfloat162*)&o2)[1] = __floats2bfloat162_rn(dz * rstd * gv.z + bv.z, dw * rstd * gv.w + bv.w);
    ((uint2*)(out + (size_t)warp * 128))[lane] = o2;
}

// ---------------- bf16 GEMM, 4-stage cp.async ring pipeline ----------------
// A bf16 [M,K] row-major, B bf16 [K,N] row-major, C = act(A@B + bias) (+res fp32).
// LNOUT: epilogue also computes per-row LN over the (N==128) output and writes bf16 LN'd tensor.
// BM=BN=128, BK=32, 256 threads, warp tile 32x64, mma.m16n8k16.
#define SA 40
#define SB 136
#define ASTG 5120            // elems per A stage (128*40)
#define BSTG 4352            // elems per B stage (32*136)
#define A_REGION (4 * ASTG)  // 20480 elems
#define GEMM_SMEM ((A_REGION + 4 * BSTG) * 2)   // 75776 bytes

template <int ACT, bool RES, bool LNOUT, typename OT>
__global__ __launch_bounds__(256, 2)
void k_gemm_b(const __nv_bfloat16* __restrict__ Ab, const __nv_bfloat16* __restrict__ Bb,
              const float* __restrict__ bias, const float* __restrict__ res,
              OT* __restrict__ C, const float* __restrict__ lng,
              const float* __restrict__ lnb, __nv_bfloat16* __restrict__ lnout,
              int M, int N, int K) {
    extern __shared__ __nv_bfloat16 smem[];
    const unsigned smbase = (unsigned)__cvta_generic_to_shared(smem);

    const int tid  = threadIdx.x;
    const int lane = tid & 31;
    const int wid  = tid >> 5;
    const int wm   = (wid >> 1) * 32;
    const int wn   = (wid & 1) * 64;
    const int g    = lane >> 2;
    const int tg   = lane & 3;
    const size_t bm = (size_t)blockIdx.x * 128;
    const size_t bn = (size_t)blockIdx.y * 128;

    const int ar = tid & 127;           // A row
    const int ah = (tid >> 7) * 16;     // A k-half
    const int br = tid >> 3;            // B k-row
    const int bc = (tid & 7) * 16;      // B col chunk

    const __nv_bfloat16* Agr = Ab + (bm + ar) * (size_t)K + ah;
    const __nv_bfloat16* Bgr = Bb + (size_t)br * N + bn + bc;

    const int lq = lane & 7, lh = (lane >> 3) & 1, lt = lane >> 4;
    const unsigned aRC = (unsigned)(((wm + lq + lh * 8) * SA + lt * 8) * 2);
    const unsigned bRC = (unsigned)(A_REGION * 2) + (unsigned)(((lq + lh * 8) * SB + wn + lt * 8) * 2);

    float acc[2][8][4];
#pragma unroll
    for (int i = 0; i < 2; ++i)
#pragma unroll
        for (int j = 0; j < 8; ++j)
#pragma unroll
            for (int r = 0; r < 4; ++r) acc[i][j][r] = 0.f;

    const int KT = K >> 5;

    // tile loader: tile kt -> stage
    auto load_tile = [&](int kt, int stage) {
        const __nv_bfloat16* An = Agr + kt * 32;
        __nv_bfloat16* ad = smem + stage * ASTG + ar * SA + ah;
        cp16b(ad,     An);
        cp16b(ad + 8, An + 8);
        const __nv_bfloat16* Bn = Bgr + (size_t)(kt * 32) * N;
        __nv_bfloat16* bd = smem + A_REGION + stage * BSTG + br * SB + bc;
        cp16b(bd,     Bn);
        cp16b(bd + 8, Bn + 8);
        cp_commit();
    };

    // prologue: tiles 0..2 into stages 0..2
    const int PRE = KT < 3 ? KT : 3;
    for (int t = 0; t < PRE; ++t) load_tile(t, t);

    for (int kt = 0; kt < KT; ++kt) {
        int allow = KT - 1 - kt; if (allow > 2) allow = 2;
        cp_wait_n(allow);
        __syncthreads();
        if (kt + 3 < KT) load_tile(kt + 3, (kt + 3) & 3);

        const int stg = kt & 3;
        const unsigned aBase = smbase + (unsigned)(stg * ASTG * 2) + aRC;
        const unsigned bBase = smbase + (unsigned)(stg * BSTG * 2) + bRC;
#pragma unroll
        for (int ks = 0; ks < 2; ++ks) {
            const unsigned kA = (unsigned)(ks * 16 * 2);
            const unsigned kB = (unsigned)(ks * 16 * SB * 2);
            unsigned af[2][4];
            ldsm4(af[0], aBase + kA);
            ldsm4(af[1], aBase + kA + (unsigned)(16 * SA * 2));
            unsigned bfr[4][4];
#pragma unroll
            for (int p = 0; p < 4; ++p)
                ldsm4t(bfr[p], bBase + kB + (unsigned)(p * 16 * 2));
#pragma unroll
            for (int mi = 0; mi < 2; ++mi)
#pragma unroll
                for (int p = 0; p < 4; ++p) {
                    mma_bf16(acc[mi][2 * p],     af[mi], bfr[p][0], bfr[p][1]);
                    mma_bf16(acc[mi][2 * p + 1], af[mi], bfr[p][2], bfr[p][3]);
                }
        }
    }

    // ---- epilogue ----
    float rs[4] = {0.f, 0.f, 0.f, 0.f};
    float rq[4] = {0.f, 0.f, 0.f, 0.f};
#pragma unroll
    for (int mi = 0; mi < 2; ++mi) {
        const size_t r0 = bm + wm + mi * 16 + g;
#pragma unroll
        for (int ni = 0; ni < 8; ++ni) {
            const size_t c0 = bn + wn + ni * 8 + 2 * tg;
            const float bx = bias[c0], by = bias[c0 + 1];
            float v0 = acc[mi][ni][0] + bx, v1 = acc[mi][ni][1] + by;
            float v2 = acc[mi][ni][2] + bx, v3 = acc[mi][ni][3] + by;
            if (ACT == 1) {
                v0 = gelu_exact(v0); v1 = gelu_exact(v1);
                v2 = gelu_exact(v2); v3 = gelu_exact(v3);
            }
            const size_t o0 = r0 * N + c0;
            const size_t o1 = (r0 + 8) * N + c0;
            if (RES) {
                float2 ra = *(const float2*)(res + o0);
                float2 rb = *(const float2*)(res + o1);
                v0 += ra.x; v1 += ra.y; v2 += rb.x; v3 += rb.y;
            }
            if (LNOUT) {
                rs[mi * 2 + 0] += v0 + v1;
                rq[mi * 2 + 0] += v0 * v0 + v1 * v1;
                rs[mi * 2 + 1] += v2 + v3;
                rq[mi * 2 + 1] += v2 * v2 + v3 * v3;
                acc[mi][ni][0] = v0; acc[mi][ni][1] = v1;
                acc[mi][ni][2] = v2; acc[mi][ni][3] = v3;
            }
            if (sizeof(OT) == 2) {
                __nv_bfloat162* Cb = (__nv_bfloat162*)C;
                Cb[o0 >> 1] = __floats2bfloat162_rn(v0, v1);
                Cb[o1 >> 1] = __floats2bfloat162_rn(v2, v3);
            } else {
                float2 w0; w0.x = v0; w0.y = v1;
                float2 w1; w1.x = v2; w1.y = v3;
                *(float2*)((float*)C + o0) = w0;
                *(float2*)((float*)C + o1) = w1;
            }
        }
    }

    if (LNOUT) {
        // cross-lane reduce over the 4-lane tg group
#pragma unroll
        for (int slot = 0; slot < 4; ++slot) {
#pragma unroll
            for (int o = 1; o < 4; o <<= 1) {
                rs[slot] += __shfl_xor_sync(0xffffffffu, rs[slot], o);
                rq[slot] += __shfl_xor_sync(0xffffffffu, rq[slot], o);
            }
        }
        __syncthreads();
        float2* sstP = (float2*)smem;          // [128][2] partials
        float2* sstF = sstP + 256;             // [128] final (mu, rstd)
        if (tg == 0) {
#pragma unroll
            for (int slot = 0; slot < 4; ++slot) {
                int r = wm + (slot >> 1) * 16 + g + (slot & 1) * 8;
                float2 p; p.x = rs[slot]; p.y = rq[slot];
                sstP[r * 2 + (wid & 1)] = p;
            }
        }
        __syncthreads();
        if (tid < 128) {
            float2 a = sstP[tid * 2], b = sstP[tid * 2 + 1];
            float s = a.x + b.x, q = a.y + b.y;
            float mu = s * (1.0f / 128.0f);
            float var = q * (1.0f / 128.0f) - mu * mu;
            float2 o2; o2.x = mu; o2.y = rsqrtf(var + 1e-5f);
            sstF[tid] = o2;
        }
        __syncthreads();
        // second pass: apply LN to held values, write bf16
#pragma unroll
        for (int mi = 0; mi < 2; ++mi) {
            const int ra = wm + mi * 16 + g;
            const float2 sa = sstF[ra];
            const float2 sb = sstF[ra + 8];
#pragma unroll
            for (int ni = 0; ni < 8; ++ni) {
                const int c = wn + ni * 8 + 2 * tg;
                const float gx = lng[c], gy = lng[c + 1];
                const float bx2 = lnb[c], by2 = lnb[c + 1];
                float l0 = (acc[mi][ni][0] - sa.x) * sa.y * gx + bx2;
                float l1 = (acc[mi][ni][1] - sa.x) * sa.y * gy + by2;
                float l2 = (acc[mi][ni][2] - sb.x) * sb.y * gx + bx2;
                float l3 = (acc[mi][ni][3] - sb.x) * sb.y * gy + by2;
                __nv_bfloat162* L = (__nv_bfloat162*)lnout;
                L[((bm + ra) * 128 + c) >> 1]     = __floats2bfloat162_rn(l0, l1);
                L[((bm + ra + 8) * 128 + c) >> 1] = __floats2bfloat162_rn(l2, l3);
            }
        }
    }
}

// ---------------- window attention (ws=2, n=4, heads=4, e=32), bf16 in/out ----------------
__global__ __launch_bounds__(128)
void k_attn(const __nv_bfloat16* __restrict__ qkv, const float* __restrict__ pos,
            __nv_bfloat16* __restrict__ att, int shifted) {
    int wid = blockIdx.x;
    int ww = wid & 31, wh = (wid >> 5) & 31, b = wid >> 10;
    __shared__ float s[4][384];
    __shared__ float spos[9];
    int tid = threadIdx.x;
    if (tid < 9) spos[tid] = pos[tid];
    {
        int i = tid >> 5, lane = tid & 31;
        int lh = i >> 1, lw = i & 1;
        int h = wh * 2 + lh, w = ww * 2 + lw;
        if (shifted) { h = (h + 1) & 63; w = (w + 1) & 63; }
        size_t t = (size_t)b * 4096 + h * 64 + w;
        const __nv_bfloat162* src = (const __nv_bfloat162*)(qkv + t * 384);
#pragma unroll
        for (int j = 0; j < 6; ++j) {
            float2 v = __bfloat1622float2(src[j * 32 + lane]);
            s[i][(j * 32 + lane) * 2]     = v.x;
            s[i][(j * 32 + lane) * 2 + 1] = v.y;
        }
    }
    __syncthreads();

    int head = tid >> 5, lane = tid & 31;
    float q[4], k[4], v[4];
#pragma unroll
    for (int i = 0; i < 4; ++i) {
        int base = (lane * 4 + head) * 3;
        q[i] = s[i][base]; k[i] = s[i][base + 1]; v[i] = s[i][base + 2];
    }
    const float scale = 0.17677669529663687f;
    float sc[4][4];
#pragma unroll
    for (int i = 0; i < 4; ++i)
#pragma unroll
        for (int j = 0; j < 4; ++j) {
            float p = q[i] * k[j];
#pragma unroll
            for (int o = 16; o; o >>= 1) p += __shfl_xor_sync(0xffffffffu, p, o);
            int dx = (j >> 1) - (i >> 1) + 1;
            int dy = (j & 1) - (i & 1) + 1;
            float w = p * scale + spos[dx * 3 + dy];
            if (shifted) {
                if (wh == 31 && ((i >> 1) != (j >> 1))) w = -1e30f;
                if (ww == 31 && ((i & 1) != (j & 1))) w = -1e30f;
            }
            sc[i][j] = w;
        }
    float out[4];
#pragma unroll
    for (int i = 0; i < 4; ++i) {
        float m = fmaxf(fmaxf(sc[i][0], sc[i][1]), fmaxf(sc[i][2], sc[i][3]));
        float e0 = expf(sc[i][0] - m), e1 = expf(sc[i][1] - m);
        float e2 = expf(sc[i][2] - m), e3 = expf(sc[i][3] - m);
        float inv = 1.0f / (e0 + e1 + e2 + e3);
        out[i] = (e0 * v[0] + e1 * v[1] + e2 * v[2] + e3 * v[3]) * inv;
    }
#pragma unroll
    for (int i = 0; i < 4; ++i) {
        int lh = i >> 1, lw = i & 1;
        int h = wh * 2 + lh, w = ww * 2 + lw;
        size_t t = (size_t)b * 4096 + h * 64 + w;
        att[t * 128 + head * 32 + lane] = __float2bfloat16(out[i]);
    }
}

// ---------------- host orchestration ----------------
extern "C" void kernel_launch(void* const* d_in, const int* in_sizes, int n_in,
                              void* d_out, int out_size) {
    const float* x    = (const float*)d_in[0];
    const float* ln_g = (const float*)d_in[1];
    const float* ln_b = (const float*)d_in[2];
    const float* wq_W = (const float*)d_in[3];
    const float* wq_b = (const float*)d_in[4];
    const float* wp_W = (const float*)d_in[5];
    const float* wp_b = (const float*)d_in[6];
    const float* wpos = (const float*)d_in[7];
    const float* sq_W = (const float*)d_in[8];
    const float* sq_b = (const float*)d_in[9];
    const float* sp_W = (const float*)d_in[10];
    const float* sp_b = (const float*)d_in[11];
    const float* spos = (const float*)d_in[12];
    const float* m1_W = (const float*)d_in[13];
    const float* m1_b = (const float*)d_in[14];
    const float* m2_W = (const float*)d_in[15];
    const float* m2_b = (const float*)d_in[16];
    float* y = (float*)d_out;

    float* p_xr;
    __nv_bfloat16 *p_ln, *p_qkv, *p_att, *p_h, *p_wb;
    cudaGetSymbolAddress((void**)&p_xr,  g_xr);
    cudaGetSymbolAddress((void**)&p_ln,  g_ln);
    cudaGetSymbolAddress((void**)&p_qkv, g_qkv);
    cudaGetSymbolAddress((void**)&p_att, g_att);
    cudaGetSymbolAddress((void**)&p_h,   g_h);
    cudaGetSymbolAddress((void**)&p_wb,  g_wb);

    static bool s_attr = false;
    if (!s_attr) {
        cudaFuncSetAttribute(k_gemm_b<0, false, false, __nv_bfloat16>,
                             cudaFuncAttributeMaxDynamicSharedMemorySize, GEMM_SMEM);
        cudaFuncSetAttribute(k_gemm_b<0, true, true, float>,
                             cudaFuncAttributeMaxDynamicSharedMemorySize, GEMM_SMEM);
        cudaFuncSetAttribute(k_gemm_b<1, false, false, __nv_bfloat16>,
                             cudaFuncAttributeMaxDynamicSharedMemorySize, GEMM_SMEM);
        cudaFuncSetAttribute(k_gemm_b<0, true, false, float>,
                             cudaFuncAttributeMaxDynamicSharedMemorySize, GEMM_SMEM);
        s_attr = true;
    }

    const int M = T_TOKENS;
    dim3 tgrid(128, 4, 32), tblk(32, 8);

    k_wconv<<<256, 256>>>(wq_W, wp_W, m1_W, m2_W, sq_W, sp_W, p_wb);
    k_transpose<<<tgrid, tblk>>>(x, p_xr);
    k_ln_bf16<<<T_TOKENS / 8, 256>>>(p_xr, ln_g, ln_b, p_ln);

    // ---- block 1: W-MSA ----
    k_gemm_b<0, false, false, __nv_bfloat16><<<dim3(M / 128, 3), 256, GEMM_SMEM>>>(
        p_ln, p_wb + W_WQ, wq_b, nullptr, p_qkv, nullptr, nullptr, nullptr, M, 384, 128);
    k_attn<<<32768, 128>>>(p_qkv, wpos, p_att, 0);
    k_gemm_b<0, true, true, float><<<dim3(M / 128, 1), 256, GEMM_SMEM>>>(
        p_att, p_wb + W_WP, wp_b, p_xr, y, ln_g, ln_b, p_ln, M, 128, 128);
    // MLP (LN'd y already in p_ln from proj epilogue)
    k_gemm_b<1, false, false, __nv_bfloat16><<<dim3(M / 128, 4), 256, GEMM_SMEM>>>(
        p_ln, p_wb + W_M1, m1_b, nullptr, p_h, nullptr, nullptr, nullptr, M, 512, 128);
    k_gemm_b<0, true, true, float><<<dim3(M / 128, 1), 256, GEMM_SMEM>>>(
        p_h, p_wb + W_M2, m2_b, y, y, ln_g, ln_b, p_ln, M, 128, 512);

    // ---- block 2: SW-MSA ----
    k_gemm_b<0, false, false, __nv_bfloat16><<<dim3(M / 128, 3), 256, GEMM_SMEM>>>(
        p_ln, p_wb + W_SQ, sq_b, nullptr, p_qkv, nullptr, nullptr, nullptr, M, 384, 128);
    k_attn<<<32768, 128>>>(p_qkv, spos, p_att, 1);
    k_gemm_b<0, true, true, float><<<dim3(M / 128, 1), 256, GEMM_SMEM>>>(
        p_att, p_wb + W_SP, sp_b, y, y, ln_g, ln_b, p_ln, M, 128, 128);
    // MLP (final — no LN output needed)
    k_gemm_b<1, false, false, __nv_bfloat16><<<dim3(M / 128, 4), 256, GEMM_SMEM>>>(
        p_ln, p_wb + W_M1, m1_b, nullptr, p_h, nullptr, nullptr, nullptr, M, 512, 128);
    k_gemm_b<0, true, false, float><<<dim3(M / 128, 1), 256, GEMM_SMEM>>>(
        p_h, p_wb + W_M2, m2_b, y, y, nullptr, nullptr, nullptr, M, 128, 512);
}

// round 13
// speedup vs baseline: 1.8839x; 1.0456x over previous
#include <cuda_runtime.h>
#include <cuda_bf16.h>
#include <math.h>

#define T_TOKENS 131072   // 32 * 64 * 64

// ---------------- scratch (device globals, no allocation) ----------------
__device__ float          g_xr [T_TOKENS * 128];   // 64 MB (fp32 residual base)
__device__ __nv_bfloat16  g_ln [T_TOKENS * 128];   // 32 MB (bf16 LN'd activations)
__device__ __nv_bfloat16  g_qkv[T_TOKENS * 384];   // 96 MB ([q|k|v], ch = head*32+e)
__device__ __nv_bfloat16  g_att[T_TOKENS * 128];   // 32 MB
__device__ __nv_bfloat16  g_h  [T_TOKENS * 512];   // 128 MB
__device__ __nv_bfloat16  g_wb [262144];           // bf16 weight pool (512 KB)
__device__ float          g_qb [768];              // permuted qkv biases (wq, sq)

// weight pool offsets
#define W_WQ 0
#define W_WP 49152
#define W_M1 65536
#define W_M2 131072
#define W_SQ 196608
#define W_SP 245760

// ---------------- helpers ----------------
__device__ __forceinline__ void mma_bf16(float c[4], const unsigned a[4], const unsigned b0, const unsigned b1) {
    asm volatile(
        "mma.sync.aligned.m16n8k16.row.col.f32.bf16.bf16.f32 "
        "{%0,%1,%2,%3}, {%4,%5,%6,%7}, {%8,%9}, {%0,%1,%2,%3};\n"
        : "+f"(c[0]), "+f"(c[1]), "+f"(c[2]), "+f"(c[3])
        : "r"(a[0]), "r"(a[1]), "r"(a[2]), "r"(a[3]), "r"(b0), "r"(b1));
}
__device__ __forceinline__ void ldsm4(unsigned r[4], unsigned addr) {
    asm volatile("ldmatrix.sync.aligned.m8n8.x4.shared.b16 {%0,%1,%2,%3}, [%4];"
        : "=r"(r[0]), "=r"(r[1]), "=r"(r[2]), "=r"(r[3]) : "r"(addr));
}
__device__ __forceinline__ void ldsm4t(unsigned r[4], unsigned addr) {
    asm volatile("ldmatrix.sync.aligned.m8n8.x4.trans.shared.b16 {%0,%1,%2,%3}, [%4];"
        : "=r"(r[0]), "=r"(r[1]), "=r"(r[2]), "=r"(r[3]) : "r"(addr));
}
__device__ __forceinline__ float gelu_exact(float x) {
    return 0.5f * x * (1.0f + erff(x * 0.70710678118654752f));
}
__device__ __forceinline__ void cp16b(__nv_bfloat16* dst, const __nv_bfloat16* src) {
    unsigned s = (unsigned)__cvta_generic_to_shared(dst);
    asm volatile("cp.async.cg.shared.global [%0], [%1], 16;\n" :: "r"(s), "l"(src));
}
__device__ __forceinline__ void cp_commit() { asm volatile("cp.async.commit_group;\n"); }
__device__ __forceinline__ void cp_wait_n(int n) {
    if (n == 0)      asm volatile("cp.async.wait_group 0;\n");
    else if (n == 1) asm volatile("cp.async.wait_group 1;\n");
    else             asm volatile("cp.async.wait_group 2;\n");
}
__device__ __forceinline__ void bf8_to_f8(uint4 u, float* f) {
    const __nv_bfloat162* h = (const __nv_bfloat162*)&u;
#pragma unroll
    for (int q = 0; q < 4; ++q) {
        float2 t = __bfloat1622float2(h[q]);
        f[2 * q] = t.x; f[2 * q + 1] = t.y;
    }
}
__device__ __forceinline__ uint4 pack8(const float* f) {
    uint4 u; __nv_bfloat162* p = (__nv_bfloat162*)&u;
#pragma unroll
    for (int j = 0; j < 4; ++j) p[j] = __floats2bfloat162_rn(f[2 * j], f[2 * j + 1]);
    return u;
}

// ---------------- weight pool conversion (fp32 -> bf16) ----------------
__global__ void k_wconv(const float* __restrict__ wq, const float* __restrict__ wp,
                        const float* __restrict__ m1, const float* __restrict__ m2,
                        const float* __restrict__ sq, const float* __restrict__ sp,
                        __nv_bfloat16* __restrict__ out) {
    int idx = (blockIdx.x * blockDim.x + threadIdx.x) * 4;
    const float* src; int base;
    if      (idx < W_WP) { src = wq; base = W_WQ; }
    else if (idx < W_M1) { src = wp; base = W_WP; }
    else if (idx < W_M2) { src = m1; base = W_M1; }
    else if (idx < W_SQ) { src = m2; base = W_M2; }
    else if (idx < W_SP) { src = sq; base = W_SQ; }
    else                 { src = sp; base = W_SP; }
    float4 v = *(const float4*)(src + (idx - base));
    *(__nv_bfloat162*)(out + idx)     = __floats2bfloat162_rn(v.x, v.y);
    *(__nv_bfloat162*)(out + idx + 2) = __floats2bfloat162_rn(v.z, v.w);
}

// permuted QKV weights: new col n' = part*128 + head*32 + e; old = (e*4+head)*3 + part
__global__ void k_wqkv(const float* __restrict__ W, const float* __restrict__ bsrc,
                       __nv_bfloat16* __restrict__ outW, float* __restrict__ outB) {
    int n = blockIdx.x * 256 + threadIdx.x;     // 49152 = 192 blocks * 256
    int kk = n / 384, np = n % 384;
    int part = np >> 7, rch = np & 127, head = rch >> 5, e = rch & 31;
    int nold = (e * 4 + head) * 3 + part;
    outW[kk * 384 + np] = __float2bfloat16(W[kk * 384 + nold]);
    if (n < 384) outB[np] = bsrc[nold];
}

// ---------------- transpose (B,C,HW) -> (B,HW,C) ----------------
__global__ void k_transpose(const float* __restrict__ x, float* __restrict__ xr) {
    __shared__ float tile[32][33];
    int b  = blockIdx.z;
    int s0 = blockIdx.x * 32;
    int c0 = blockIdx.y * 32;
    const float* xb = x + (size_t)b * 128 * 4096;
    int tx = threadIdx.x, ty = threadIdx.y;  // 32 x 8
#pragma unroll
    for (int i = 0; i < 32; i += 8)
        tile[ty + i][tx] = xb[(size_t)(c0 + ty + i) * 4096 + s0 + tx];
    __syncthreads();
    float* xrb = xr + (size_t)b * 4096 * 128;
#pragma unroll
    for (int i = 0; i < 32; i += 8)
        xrb[(size_t)(s0 + ty + i) * 128 + c0 + tx] = tile[tx][ty + i];
}

// ---------------- LN (fp32 in -> bf16 out), one warp per token ----------------
__global__ void k_ln_bf16(const float* __restrict__ in, const float* __restrict__ g,
                          const float* __restrict__ bta, __nv_bfloat16* __restrict__ out) {
    int warp = (blockIdx.x * blockDim.x + threadIdx.x) >> 5;
    int lane = threadIdx.x & 31;
    if (warp >= T_TOKENS) return;
    float4 v = ((const float4*)(in + (size_t)warp * 128))[lane];
    float s = v.x + v.y + v.z + v.w;
#pragma unroll
    for (int o = 16; o; o >>= 1) s += __shfl_xor_sync(0xffffffffu, s, o);
    float mu = s * (1.0f / 128.0f);
    float dx = v.x - mu, dy = v.y - mu, dz = v.z - mu, dw = v.w - mu;
    float q = dx * dx + dy * dy + dz * dz + dw * dw;
#pragma unroll
    for (int o = 16; o; o >>= 1) q += __shfl_xor_sync(0xffffffffu, q, o);
    float rstd = rsqrtf(q * (1.0f / 128.0f) + 1e-5f);
    float4 gv = ((const float4*)g)[lane];
    float4 bv = ((const float4*)bta)[lane];
    uint2 o2;
    ((__nv_bfloat162*)&o2)[0] = __floats2bfloat162_rn(dx * rstd * gv.x + bv.x, dy * rstd * gv.y + bv.y);
    ((__nv_bfloat162*)&o2)[1] = __floats2bfloat162_rn(dz * rstd * gv.z + bv.z, dw * rstd * gv.w + bv.w);
    ((uint2*)(out + (size_t)warp * 128))[lane] = o2;
}

// ---------------- bf16 GEMM, 4-stage cp.async ring pipeline ----------------
#define SA 40
#define SB 136
#define ASTG 5120
#define BSTG 4352
#define A_REGION (4 * ASTG)
#define GEMM_SMEM ((A_REGION + 4 * BSTG) * 2)   // 75776 bytes

template <int ACT, bool RES, bool LNOUT, typename OT>
__global__ __launch_bounds__(256, 2)
void k_gemm_b(const __nv_bfloat16* __restrict__ Ab, const __nv_bfloat16* __restrict__ Bb,
              const float* __restrict__ bias, const float* __restrict__ res,
              OT* __restrict__ C, const float* __restrict__ lng,
              const float* __restrict__ lnb, __nv_bfloat16* __restrict__ lnout,
              int M, int N, int K) {
    extern __shared__ __nv_bfloat16 smem[];
    const unsigned smbase = (unsigned)__cvta_generic_to_shared(smem);

    const int tid  = threadIdx.x;
    const int lane = tid & 31;
    const int wid  = tid >> 5;
    const int wm   = (wid >> 1) * 32;
    const int wn   = (wid & 1) * 64;
    const int g    = lane >> 2;
    const int tg   = lane & 3;
    const size_t bm = (size_t)blockIdx.x * 128;
    const size_t bn = (size_t)blockIdx.y * 128;

    const int ar = tid & 127;
    const int ah = (tid >> 7) * 16;
    const int br = tid >> 3;
    const int bc = (tid & 7) * 16;

    const __nv_bfloat16* Agr = Ab + (bm + ar) * (size_t)K + ah;
    const __nv_bfloat16* Bgr = Bb + (size_t)br * N + bn + bc;

    const int lq = lane & 7, lh = (lane >> 3) & 1, lt = lane >> 4;
    const unsigned aRC = (unsigned)(((wm + lq + lh * 8) * SA + lt * 8) * 2);
    const unsigned bRC = (unsigned)(A_REGION * 2) + (unsigned)(((lq + lh * 8) * SB + wn + lt * 8) * 2);

    float acc[2][8][4];
#pragma unroll
    for (int i = 0; i < 2; ++i)
#pragma unroll
        for (int j = 0; j < 8; ++j)
#pragma unroll
            for (int r = 0; r < 4; ++r) acc[i][j][r] = 0.f;

    const int KT = K >> 5;

    auto load_tile = [&](int kt, int stage) {
        const __nv_bfloat16* An = Agr + kt * 32;
        __nv_bfloat16* ad = smem + stage * ASTG + ar * SA + ah;
        cp16b(ad,     An);
        cp16b(ad + 8, An + 8);
        const __nv_bfloat16* Bn = Bgr + (size_t)(kt * 32) * N;
        __nv_bfloat16* bd = smem + A_REGION + stage * BSTG + br * SB + bc;
        cp16b(bd,     Bn);
        cp16b(bd + 8, Bn + 8);
        cp_commit();
    };

    const int PRE = KT < 3 ? KT : 3;
    for (int t = 0; t < PRE; ++t) load_tile(t, t);

    for (int kt = 0; kt < KT; ++kt) {
        int allow = KT - 1 - kt; if (allow > 2) allow = 2;
        cp_wait_n(allow);
        __syncthreads();
        if (kt + 3 < KT) load_tile(kt + 3, (kt + 3) & 3);

        const int stg = kt & 3;
        const unsigned aBase = smbase + (unsigned)(stg * ASTG * 2) + aRC;
        const unsigned bBase = smbase + (unsigned)(stg * BSTG * 2) + bRC;
#pragma unroll
        for (int ks = 0; ks < 2; ++ks) {
            const unsigned kA = (unsigned)(ks * 16 * 2);
            const unsigned kB = (unsigned)(ks * 16 * SB * 2);
            unsigned af[2][4];
            ldsm4(af[0], aBase + kA);
            ldsm4(af[1], aBase + kA + (unsigned)(16 * SA * 2));
            unsigned bfr[4][4];
#pragma unroll
            for (int p = 0; p < 4; ++p)
                ldsm4t(bfr[p], bBase + kB + (unsigned)(p * 16 * 2));
#pragma unroll
            for (int mi = 0; mi < 2; ++mi)
#pragma unroll
                for (int p = 0; p < 4; ++p) {
                    mma_bf16(acc[mi][2 * p],     af[mi], bfr[p][0], bfr[p][1]);
                    mma_bf16(acc[mi][2 * p + 1], af[mi], bfr[p][2], bfr[p][3]);
                }
        }
    }

    // ---- epilogue ----
    float rs[4] = {0.f, 0.f, 0.f, 0.f};
    float rq[4] = {0.f, 0.f, 0.f, 0.f};
#pragma unroll
    for (int mi = 0; mi < 2; ++mi) {
        const size_t r0 = bm + wm + mi * 16 + g;
#pragma unroll
        for (int ni = 0; ni < 8; ++ni) {
            const size_t c0 = bn + wn + ni * 8 + 2 * tg;
            const float bx = bias[c0], by = bias[c0 + 1];
            float v0 = acc[mi][ni][0] + bx, v1 = acc[mi][ni][1] + by;
            float v2 = acc[mi][ni][2] + bx, v3 = acc[mi][ni][3] + by;
            if (ACT == 1) {
                v0 = gelu_exact(v0); v1 = gelu_exact(v1);
                v2 = gelu_exact(v2); v3 = gelu_exact(v3);
            }
            const size_t o0 = r0 * N + c0;
            const size_t o1 = (r0 + 8) * N + c0;
            if (RES) {
                float2 ra = *(const float2*)(res + o0);
                float2 rb = *(const float2*)(res + o1);
                v0 += ra.x; v1 += ra.y; v2 += rb.x; v3 += rb.y;
            }
            if (LNOUT) {
                rs[mi * 2 + 0] += v0 + v1;
                rq[mi * 2 + 0] += v0 * v0 + v1 * v1;
                rs[mi * 2 + 1] += v2 + v3;
                rq[mi * 2 + 1] += v2 * v2 + v3 * v3;
                acc[mi][ni][0] = v0; acc[mi][ni][1] = v1;
                acc[mi][ni][2] = v2; acc[mi][ni][3] = v3;
            }
            if (sizeof(OT) == 2) {
                __nv_bfloat162* Cb = (__nv_bfloat162*)C;
                Cb[o0 >> 1] = __floats2bfloat162_rn(v0, v1);
                Cb[o1 >> 1] = __floats2bfloat162_rn(v2, v3);
            } else {
                float2 w0; w0.x = v0; w0.y = v1;
                float2 w1; w1.x = v2; w1.y = v3;
                *(float2*)((float*)C + o0) = w0;
                *(float2*)((float*)C + o1) = w1;
            }
        }
    }

    if (LNOUT) {
#pragma unroll
        for (int slot = 0; slot < 4; ++slot) {
#pragma unroll
            for (int o = 1; o < 4; o <<= 1) {
                rs[slot] += __shfl_xor_sync(0xffffffffu, rs[slot], o);
                rq[slot] += __shfl_xor_sync(0xffffffffu, rq[slot], o);
            }
        }
        __syncthreads();
        float2* sstP = (float2*)smem;
        float2* sstF = sstP + 256;
        if (tg == 0) {
#pragma unroll
            for (int slot = 0; slot < 4; ++slot) {
                int r = wm + (slot >> 1) * 16 + g + (slot & 1) * 8;
                float2 p; p.x = rs[slot]; p.y = rq[slot];
                sstP[r * 2 + (wid & 1)] = p;
            }
        }
        __syncthreads();
        if (tid < 128) {
            float2 a = sstP[tid * 2], b = sstP[tid * 2 + 1];
            float s = a.x + b.x, q = a.y + b.y;
            float mu = s * (1.0f / 128.0f);
            float var = q * (1.0f / 128.0f) - mu * mu;
            float2 o2; o2.x = mu; o2.y = rsqrtf(var + 1e-5f);
            sstF[tid] = o2;
        }
        __syncthreads();
#pragma unroll
        for (int mi = 0; mi < 2; ++mi) {
            const int ra = wm + mi * 16 + g;
            const float2 sa = sstF[ra];
            const float2 sb = sstF[ra + 8];
#pragma unroll
            for (int ni = 0; ni < 8; ++ni) {
                const int c = wn + ni * 8 + 2 * tg;
                const float gx = lng[c], gy = lng[c + 1];
                const float bx2 = lnb[c], by2 = lnb[c + 1];
                float l0 = (acc[mi][ni][0] - sa.x) * sa.y * gx + bx2;
                float l1 = (acc[mi][ni][1] - sa.x) * sa.y * gy + by2;
                float l2 = (acc[mi][ni][2] - sb.x) * sb.y * gx + bx2;
                float l3 = (acc[mi][ni][3] - sb.x) * sb.y * gy + by2;
                __nv_bfloat162* L = (__nv_bfloat162*)lnout;
                L[((bm + ra) * 128 + c) >> 1]     = __floats2bfloat162_rn(l0, l1);
                L[((bm + ra + 8) * 128 + c) >> 1] = __floats2bfloat162_rn(l2, l3);
            }
        }
    }
}

// ---------------- window attention v2: strip-based, zero shfl ----------------
// qkv layout: [token][q(128)|k(128)|v(128)], ch = head*32+e.
// One block = one 2-row strip (128 tokens = 32 windows). 256 threads:
// thread = (win 0..31, head 0..3, ih 0..1); ih selects the query row.
#define AIN 392
#define AOUT 136
#define ATT_SMEM ((128 * AIN + 128 * AOUT) * 2)   // 135168 bytes

__global__ __launch_bounds__(256)
void k_attn2(const __nv_bfloat16* __restrict__ qkv, const float* __restrict__ pos,
             __nv_bfloat16* __restrict__ att, int shifted) {
    extern __shared__ __nv_bfloat16 sm2[];
    __nv_bfloat16* sin  = sm2;                 // [128][392]
    __nv_bfloat16* sout = sm2 + 128 * AIN;     // [128][136]
    __shared__ float spos[9];
    const int tid = threadIdx.x;
    const int b = blockIdx.x >> 5, s = blockIdx.x & 31;
    if (tid < 9) spos[tid] = pos[tid];

    // ---- load 128 tokens x 384 ch (source gather for shifted) ----
    // each thread owns (token, 192-ch half) = 384 bytes = 24 uint4 (R11 bug: was 12)
    {
        const int tok  = tid >> 1;           // 0..127
        const int half = tid & 1;            // 0..1 (192-ch half)
        const int r    = tok >> 6;           // strip-local row
        const int c    = tok & 63;           // dest col
        const int gr   = shifted ? ((2 * s + 1 + r) & 63) : (2 * s + r);
        const int gc   = shifted ? ((c + 1) & 63) : c;
        const __nv_bfloat16* src = qkv + ((size_t)b * 4096 + gr * 64 + gc) * 384 + half * 192;
        __nv_bfloat16* dst = sin + tok * AIN + half * 192;
#pragma unroll
        for (int i = 0; i < 24; ++i)
            ((uint4*)dst)[i] = ((const uint4*)src)[i];
    }
    __syncthreads();

    // ---- per-thread attention ----
    const int win  = tid >> 3;
    const int head = (tid >> 1) & 3;
    const int ih   = tid & 1;
    const int qch  = head * 32;
    const int t0 = ih * 64 + win * 2;        // query (lh=ih, lw=0)
    const int t1 = t0 + 1;                   // query (lh=ih, lw=1)
    int tk[4];
#pragma unroll
    for (int j = 0; j < 4; ++j) tk[j] = (j >> 1) * 64 + win * 2 + (j & 1);

    float d[2][4] = {{0.f, 0.f, 0.f, 0.f}, {0.f, 0.f, 0.f, 0.f}};
#pragma unroll
    for (int c = 0; c < 4; ++c) {
        float qa[8], qb[8];
        bf8_to_f8(*(const uint4*)&sin[t0 * AIN + qch + c * 8], qa);
        bf8_to_f8(*(const uint4*)&sin[t1 * AIN + qch + c * 8], qb);
#pragma unroll
        for (int j = 0; j < 4; ++j) {
            float kf[8];
            bf8_to_f8(*(const uint4*)&sin[tk[j] * AIN + 128 + qch + c * 8], kf);
#pragma unroll
            for (int ch = 0; ch < 8; ++ch) {
                d[0][j] += qa[ch] * kf[ch];
                d[1][j] += qb[ch] * kf[ch];
            }
        }
    }

    const float scale = 0.17677669529663687f;   // 1/sqrt(32)
    float p[2][4];
#pragma unroll
    for (int i2 = 0; i2 < 2; ++i2) {
        float w[4];
#pragma unroll
        for (int j = 0; j < 4; ++j) {
            int dx = (j >> 1) - ih + 1;
            int dy = (j & 1) - i2 + 1;
            float v = d[i2][j] * scale + spos[dx * 3 + dy];
            if (shifted) {
                if (s == 31 && ((j >> 1) != ih)) v = -1e30f;
                if (win == 31 && ((j & 1) != i2)) v = -1e30f;
            }
            w[j] = v;
        }
        float m = fmaxf(fmaxf(w[0], w[1]), fmaxf(w[2], w[3]));
        float e0 = __expf(w[0] - m), e1 = __expf(w[1] - m);
        float e2 = __expf(w[2] - m), e3 = __expf(w[3] - m);
        float inv = 1.0f / (e0 + e1 + e2 + e3);
        p[i2][0] = e0 * inv; p[i2][1] = e1 * inv;
        p[i2][2] = e2 * inv; p[i2][3] = e3 * inv;
    }

    // AV + store
#pragma unroll
    for (int c = 0; c < 4; ++c) {
        float o0[8] = {0,0,0,0,0,0,0,0}, o1[8] = {0,0,0,0,0,0,0,0};
#pragma unroll
        for (int j = 0; j < 4; ++j) {
            float vf[8];
            bf8_to_f8(*(const uint4*)&sin[tk[j] * AIN + 256 + qch + c * 8], vf);
#pragma unroll
            for (int ch = 0; ch < 8; ++ch) {
                o0[ch] += p[0][j] * vf[ch];
                o1[ch] += p[1][j] * vf[ch];
            }
        }
        *(uint4*)&sout[t0 * AOUT + qch + c * 8] = pack8(o0);
        *(uint4*)&sout[t1 * AOUT + qch + c * 8] = pack8(o1);
    }
    __syncthreads();

    // ---- coalesced store to g_att (dest rows = 2s, 2s+1) ----
    const size_t gbase = ((size_t)b * 4096 + (size_t)(2 * s) * 64) * 128;
#pragma unroll
    for (int q = 0; q < 8; ++q) {
        int idx = q * 256 + tid;             // 0..2047
        int tok = idx >> 4, c8 = idx & 15;
        *(uint4*)(att + gbase + (size_t)tok * 128 + c8 * 8) =
            *(const uint4*)&sout[tok * AOUT + c8 * 8];
    }
}

// ---------------- host orchestration ----------------
extern "C" void kernel_launch(void* const* d_in, const int* in_sizes, int n_in,
                              void* d_out, int out_size) {
    const float* x    = (const float*)d_in[0];
    const float* ln_g = (const float*)d_in[1];
    const float* ln_b = (const float*)d_in[2];
    const float* wq_W = (const float*)d_in[3];
    const float* wq_b = (const float*)d_in[4];
    const float* wp_W = (const float*)d_in[5];
    const float* wp_b = (const float*)d_in[6];
    const float* wpos = (const float*)d_in[7];
    const float* sq_W = (const float*)d_in[8];
    const float* sq_b = (const float*)d_in[9];
    const float* sp_W = (const float*)d_in[10];
    const float* sp_b = (const float*)d_in[11];
    const float* spos = (const float*)d_in[12];
    const float* m1_W = (const float*)d_in[13];
    const float* m1_b = (const float*)d_in[14];
    const float* m2_W = (const float*)d_in[15];
    const float* m2_b = (const float*)d_in[16];
    float* y = (float*)d_out;

    float *p_xr, *p_qb;
    __nv_bfloat16 *p_ln, *p_qkv, *p_att, *p_h, *p_wb;
    cudaGetSymbolAddress((void**)&p_xr,  g_xr);
    cudaGetSymbolAddress((void**)&p_ln,  g_ln);
    cudaGetSymbolAddress((void**)&p_qkv, g_qkv);
    cudaGetSymbolAddress((void**)&p_att, g_att);
    cudaGetSymbolAddress((void**)&p_h,   g_h);
    cudaGetSymbolAddress((void**)&p_wb,  g_wb);
    cudaGetSymbolAddress((void**)&p_qb,  g_qb);

    static bool s_attr = false;
    if (!s_attr) {
        cudaFuncSetAttribute(k_gemm_b<0, false, false, __nv_bfloat16>,
                             cudaFuncAttributeMaxDynamicSharedMemorySize, GEMM_SMEM);
        cudaFuncSetAttribute(k_gemm_b<0, true, true, float>,
                             cudaFuncAttributeMaxDynamicSharedMemorySize, GEMM_SMEM);
        cudaFuncSetAttribute(k_gemm_b<1, false, false, __nv_bfloat16>,
                             cudaFuncAttributeMaxDynamicSharedMemorySize, GEMM_SMEM);
        cudaFuncSetAttribute(k_gemm_b<0, true, false, float>,
                             cudaFuncAttributeMaxDynamicSharedMemorySize, GEMM_SMEM);
        cudaFuncSetAttribute(k_attn2,
                             cudaFuncAttributeMaxDynamicSharedMemorySize, ATT_SMEM);
        s_attr = true;
    }

    const int M = T_TOKENS;
    dim3 tgrid(128, 4, 32), tblk(32, 8);

    k_wconv<<<256, 256>>>(wq_W, wp_W, m1_W, m2_W, sq_W, sp_W, p_wb);
    k_wqkv<<<192, 256>>>(wq_W, wq_b, p_wb + W_WQ, p_qb);
    k_wqkv<<<192, 256>>>(sq_W, sq_b, p_wb + W_SQ, p_qb + 384);
    k_transpose<<<tgrid, tblk>>>(x, p_xr);
    k_ln_bf16<<<T_TOKENS / 8, 256>>>(p_xr, ln_g, ln_b, p_ln);

    // ---- block 1: W-MSA ----
    k_gemm_b<0, false, false, __nv_bfloat16><<<dim3(M / 128, 3), 256, GEMM_SMEM>>>(
        p_ln, p_wb + W_WQ, p_qb, nullptr, p_qkv, nullptr, nullptr, nullptr, M, 384, 128);
    k_attn2<<<1024, 256, ATT_SMEM>>>(p_qkv, wpos, p_att, 0);
    k_gemm_b<0, true, true, float><<<dim3(M / 128, 1), 256, GEMM_SMEM>>>(
        p_att, p_wb + W_WP, wp_b, p_xr, y, ln_g, ln_b, p_ln, M, 128, 128);
    // MLP
    k_gemm_b<1, false, false, __nv_bfloat16><<<dim3(M / 128, 4), 256, GEMM_SMEM>>>(
        p_ln, p_wb + W_M1, m1_b, nullptr, p_h, nullptr, nullptr, nullptr, M, 512, 128);
    k_gemm_b<0, true, true, float><<<dim3(M / 128, 1), 256, GEMM_SMEM>>>(
        p_h, p_wb + W_M2, m2_b, y, y, ln_g, ln_b, p_ln, M, 128, 512);

    // ---- block 2: SW-MSA ----
    k_gemm_b<0, false, false, __nv_bfloat16><<<dim3(M / 128, 3), 256, GEMM_SMEM>>>(
        p_ln, p_wb + W_SQ, p_qb + 384, nullptr, p_qkv, nullptr, nullptr, nullptr, M, 384, 128);
    k_attn2<<<1024, 256, ATT_SMEM>>>(p_qkv, spos, p_att, 1);
    k_gemm_b<0, true, true, float><<<dim3(M / 128, 1), 256, GEMM_SMEM>>>(
        p_att, p_wb + W_SP, sp_b, y, y, ln_g, ln_b, p_ln, M, 128, 128);
    // MLP (final)
    k_gemm_b<1, false, false, __nv_bfloat16><<<dim3(M / 128, 4), 256, GEMM_SMEM>>>(
        p_ln, p_wb + W_M1, m1_b, nullptr, p_h, nullptr, nullptr, nullptr, M, 512, 128);
    k_gemm_b<0, true, false, float><<<dim3(M / 128, 1), 256, GEMM_SMEM>>>(
        p_h, p_wb + W_M2, m2_b, y, y, nullptr, nullptr, nullptr, M, 128, 512);
}